// round 1
// baseline (speedup 1.0000x reference)
#include <cuda_runtime.h>
#include <math.h>

// Problem constants
#define B_    32
#define T_    512
#define C_    1024
#define H_    16
#define D_    64
#define M_TOT (B_ * T_)          // 16384 rows
#define N_QKV (3 * C_)           // 3072
#define NEG_BIG (-1.0e30f)

// Scratch (device globals: no allocations allowed)
__device__ float g_q[B_ * H_ * T_ * D_];    // [B,H,T,D]
__device__ float g_k[B_ * H_ * T_ * D_];
__device__ float g_v[B_ * H_ * T_ * D_];
__device__ float g_att[B_ * T_ * C_];       // [B,T,C] attention output

// ---------------------------------------------------------------------------
// SIMT fp32 GEMM: out = A[M,K] @ W[K,N] + bias
// EPI == 1 : A = x (param), epilogue scatters into g_q/g_k/g_v ([B,H,T,D])
// EPI == 0 : A = g_att (ignores param), epilogue writes plain [M,N] + bias
// Tiles: 128x128x16, 256 threads, 8x8 per thread.
// Requires M%128==0, N%128==0, K%16==0 (true for all our shapes).
// ---------------------------------------------------------------------------
template <int EPI>
__global__ __launch_bounds__(256) void sgemm_kernel(
    const float* __restrict__ A,
    const float* __restrict__ W,
    const float* __restrict__ bias,
    float* __restrict__ out,
    int M, int N, int K)
{
    __shared__ float As[16][132];   // [k][m], padded
    __shared__ float Bs[16][128];   // [k][n]

    const int tid = threadIdx.x;
    const int tx  = tid & 15;       // 0..15 -> N direction
    const int ty  = tid >> 4;       // 0..15 -> M direction
    const int bx  = blockIdx.x;     // N tile
    const int by  = blockIdx.y;     // M tile

    const float* Abase = (EPI == 1) ? A : g_att;
    const float* Ablk  = Abase + (size_t)(by * 128) * K;
    const float* Wblk  = W + bx * 128;

    float acc[8][8];
#pragma unroll
    for (int i = 0; i < 8; i++)
#pragma unroll
        for (int j = 0; j < 8; j++) acc[i][j] = 0.0f;

    for (int k0 = 0; k0 < K; k0 += 16) {
        // Load A tile (128 rows x 16 k), transpose into As[k][m]
#pragma unroll
        for (int i = 0; i < 2; i++) {
            int f   = tid + 256 * i;      // 0..511 float4 id
            int row = f >> 2;             // 0..127
            int c4  = f & 3;              // 0..3 (k/4)
            float4 v = *(const float4*)(Ablk + (size_t)row * K + k0 + c4 * 4);
            As[c4 * 4 + 0][row] = v.x;
            As[c4 * 4 + 1][row] = v.y;
            As[c4 * 4 + 2][row] = v.z;
            As[c4 * 4 + 3][row] = v.w;
        }
        // Load W tile (16 k x 128 n) directly
#pragma unroll
        for (int i = 0; i < 2; i++) {
            int f   = tid + 256 * i;
            int row = f >> 5;             // 0..15
            int c4  = f & 31;             // 0..31
            *(float4*)(&Bs[row][c4 * 4]) =
                *(const float4*)(Wblk + (size_t)(k0 + row) * N + c4 * 4);
        }
        __syncthreads();

#pragma unroll
        for (int kk = 0; kk < 16; kk++) {
            float4 a0 = *(const float4*)(&As[kk][ty * 8]);
            float4 a1 = *(const float4*)(&As[kk][ty * 8 + 4]);
            float4 b0 = *(const float4*)(&Bs[kk][tx * 8]);
            float4 b1 = *(const float4*)(&Bs[kk][tx * 8 + 4]);
            float a[8] = {a0.x, a0.y, a0.z, a0.w, a1.x, a1.y, a1.z, a1.w};
            float b[8] = {b0.x, b0.y, b0.z, b0.w, b1.x, b1.y, b1.z, b1.w};
#pragma unroll
            for (int i = 0; i < 8; i++)
#pragma unroll
                for (int j = 0; j < 8; j++) acc[i][j] += a[i] * b[j];
        }
        __syncthreads();
    }

    // Epilogue
#pragma unroll
    for (int i = 0; i < 8; i++) {
        int mrow = by * 128 + ty * 8 + i;
#pragma unroll
        for (int j = 0; j < 8; j++) {
            int n = bx * 128 + tx * 8 + j;
            float val = acc[i][j] + bias[n];
            if (EPI == 1) {
                // scatter into [B,H,T,D] q/k/v
                int b   = mrow >> 9;          // /512
                int t   = mrow & 511;
                int sec = n >> 10;            // 0=q 1=k 2=v (uniform per block)
                int c   = n & 1023;
                int h   = c >> 6;
                int d   = c & 63;
                float* dst = (sec == 0) ? g_q : ((sec == 1) ? g_k : g_v);
                dst[((b * H_ + h) * T_ + t) * D_ + d] = val;
            } else {
                out[(size_t)mrow * N + n] = val;
            }
        }
    }
}

// ---------------------------------------------------------------------------
// Causal flash attention, fp32, online softmax.
// Grid: (T/64, B*H). Block: 64 threads; thread t owns query row qt*64+t.
// K/V tiles staged in smem (broadcast reads). Scores staged in swizzled
// smem buffer (reuses Q staging area).
// ---------------------------------------------------------------------------
__global__ __launch_bounds__(64) void attn_kernel()
{
    __shared__ __align__(16) float Ks[64 * 64];
    __shared__ __align__(16) float Vs[64 * 64];
    __shared__ __align__(16) float Qs[64 * 64];   // Q staging, then scores

    const int t  = threadIdx.x;       // 0..63
    const int qt = blockIdx.x;        // query tile 0..7
    const int bh = blockIdx.y;        // 0..511
    const int b  = bh >> 4;
    const int h  = bh & 15;

    const float* Qg = g_q + (size_t)bh * T_ * D_;
    const float* Kg = g_k + (size_t)bh * T_ * D_;
    const float* Vg = g_v + (size_t)bh * T_ * D_;

    // Stage Q tile (coalesced), swizzled store: Qs[row*64 + (col+row)&63]
    for (int idx = t, r = 0; r < 64; idx += 64, r++) {
        // idx = r*64 + t  -> row r, col t
        Qs[r * 64 + ((t + r) & 63)] = Qg[(qt * 64 + r) * 64 + t];
    }
    __syncthreads();

    float q[64];
#pragma unroll
    for (int d = 0; d < 64; d++) q[d] = Qs[t * 64 + ((d + t) & 63)];
    __syncthreads();   // Qs now free for score staging

    float acc[64];
#pragma unroll
    for (int d = 0; d < 64; d++) acc[d] = 0.0f;
    float m = NEG_BIG;
    float l = 0.0f;

    const int qidx = qt * 64 + t;
    const float scale = 0.125f;       // 1/sqrt(64)

    for (int jt = 0; jt <= qt; jt++) {
        // Stage K,V tiles (float4, coalesced)
        const float4* K4g = (const float4*)(Kg + jt * 64 * 64);
        const float4* V4g = (const float4*)(Vg + jt * 64 * 64);
        float4* K4 = (float4*)Ks;
        float4* V4 = (float4*)Vs;
#pragma unroll
        for (int i = 0; i < 16; i++) {
            K4[t + 64 * i] = K4g[t + 64 * i];
            V4[t + 64 * i] = V4g[t + 64 * i];
        }
        __syncthreads();

        const bool diag = (jt == qt);
        // Pass 1: scores + tile max
        float tm = NEG_BIG;
        for (int j = 0; j < 64; j++) {
            float s = 0.0f;
#pragma unroll
            for (int d = 0; d < 64; d++) s += q[d] * Ks[j * 64 + d];
            s *= scale;
            if (diag && (jt * 64 + j) > qidx) s = NEG_BIG;   // causal mask
            Qs[t * 64 + ((j + t) & 63)] = s;
            tm = fmaxf(tm, s);
        }
        float mnew = fmaxf(m, tm);
        float corr = __expf(m - mnew);
        l *= corr;
#pragma unroll
        for (int d = 0; d < 64; d++) acc[d] *= corr;

        // Pass 2: exp + PV accumulate
        for (int j = 0; j < 64; j++) {
            float p = __expf(Qs[t * 64 + ((j + t) & 63)] - mnew);
            l += p;
#pragma unroll
            for (int d = 0; d < 64; d++) acc[d] += p * Vs[j * 64 + d];
        }
        m = mnew;
        __syncthreads();
    }

    // Write to g_att in [B,T,C] layout: row (b, qt*64+t), cols h*64..h*64+63
    float inv = 1.0f / l;
    float* outp = g_att + ((size_t)(b * T_ + qt * 64 + t)) * C_ + h * D_;
#pragma unroll
    for (int d4 = 0; d4 < 16; d4++) {
        float4 v;
        v.x = acc[d4 * 4 + 0] * inv;
        v.y = acc[d4 * 4 + 1] * inv;
        v.z = acc[d4 * 4 + 2] * inv;
        v.w = acc[d4 * 4 + 3] * inv;
        *(float4*)(outp + d4 * 4) = v;
    }
}

// ---------------------------------------------------------------------------
// Launch
// ---------------------------------------------------------------------------
extern "C" void kernel_launch(void* const* d_in, const int* in_sizes, int n_in,
                              void* d_out, int out_size)
{
    const float* x     = (const float*)d_in[0];   // [32,512,1024]
    const float* w_qkv = (const float*)d_in[1];   // [1024,3072]
    const float* b_qkv = (const float*)d_in[2];   // [3072]
    const float* w_out = (const float*)d_in[3];   // [1024,1024]
    const float* b_out = (const float*)d_in[4];   // [1024]
    float* out = (float*)d_out;                   // [32,512,1024]

    // 1) QKV projection + bias, scatter to [B,H,T,D]
    {
        dim3 grid(N_QKV / 128, M_TOT / 128);      // (24, 128)
        sgemm_kernel<1><<<grid, 256>>>(x, w_qkv, b_qkv, nullptr,
                                       M_TOT, N_QKV, C_);
    }
    // 2) Causal flash attention -> g_att [B,T,C]
    {
        dim3 grid(T_ / 64, B_ * H_);              // (8, 512)
        attn_kernel<<<grid, 64>>>();
    }
    // 3) Output projection + bias -> d_out
    {
        dim3 grid(C_ / 128, M_TOT / 128);         // (8, 128)
        sgemm_kernel<0><<<grid, 256>>>(nullptr, w_out, b_out, out,
                                       M_TOT, C_, C_);
    }
}

// round 4
// speedup vs baseline: 2.0441x; 2.0441x over previous
#include <cuda_runtime.h>
#include <stdint.h>
#include <math.h>

// Problem constants
#define B_    32
#define T_    512
#define C_    1024
#define H_    16
#define D_    64
#define M_TOT (B_ * T_)          // 16384
#define N_QKV (3 * C_)           // 3072
#define NEG_BIG (-1.0e30f)

// Scratch (device globals: no allocations allowed)
__device__ float g_q[B_ * H_ * T_ * D_];    // [B,H,T,D]
__device__ float g_k[B_ * H_ * T_ * D_];
__device__ float g_v[B_ * H_ * T_ * D_];
__device__ float g_att[B_ * T_ * C_];       // [B,T,C] attention out (tf32-rounded)
__device__ float g_xc[M_TOT * C_];          // tf32-rounded x
__device__ float g_wqkvc[C_ * N_QKV];       // tf32-rounded w_qkv
__device__ float g_woutc[C_ * C_];          // tf32-rounded w_out

// ---------------------------------------------------------------------------
// Helpers
// ---------------------------------------------------------------------------
__device__ __forceinline__ uint32_t to_tf32_bits(float x) {
    uint32_t y;
    asm("cvt.rna.tf32.f32 %0, %1;" : "=r"(y) : "f"(x));
    return y;
}
__device__ __forceinline__ float to_tf32(float x) {
    return __uint_as_float(to_tf32_bits(x));
}

__device__ __forceinline__ uint32_t smem_u32(const void* p) {
    return (uint32_t)__cvta_generic_to_shared(p);
}

__device__ __forceinline__ void cp_async16(uint32_t dst, const void* src) {
    asm volatile("cp.async.cg.shared.global [%0], [%1], 16;\n" :: "r"(dst), "l"(src));
}
__device__ __forceinline__ void cp_commit() {
    asm volatile("cp.async.commit_group;\n" ::);
}
__device__ __forceinline__ void cp_wait0() {
    asm volatile("cp.async.wait_group 0;\n" ::);
}

__device__ __forceinline__ void mma_tf32(float* c, const uint32_t* a, const uint32_t* b) {
    asm volatile(
        "mma.sync.aligned.m16n8k8.row.col.f32.tf32.tf32.f32 "
        "{%0,%1,%2,%3}, {%4,%5,%6,%7}, {%8,%9}, {%0,%1,%2,%3};\n"
        : "+f"(c[0]), "+f"(c[1]), "+f"(c[2]), "+f"(c[3])
        : "r"(a[0]), "r"(a[1]), "r"(a[2]), "r"(a[3]),
          "r"(b[0]), "r"(b[1]));
}

// ---------------------------------------------------------------------------
// TF32 round kernel: out[i] = rna_tf32(in[i]); sel picks destination global.
// ---------------------------------------------------------------------------
__global__ __launch_bounds__(256) void cvt_tf32_kernel(
    const float* __restrict__ in, int sel, int n4)
{
    float* out = (sel == 0) ? g_xc : (sel == 1) ? g_wqkvc : g_woutc;
    int i = blockIdx.x * blockDim.x + threadIdx.x;
    if (i < n4) {
        float4 v = ((const float4*)in)[i];
        v.x = to_tf32(v.x);
        v.y = to_tf32(v.y);
        v.z = to_tf32(v.z);
        v.w = to_tf32(v.w);
        ((float4*)out)[i] = v;
    }
}

// ---------------------------------------------------------------------------
// TF32 tensor-core GEMM: out = A[M,K] @ W[K,N] + bias
// EPI == 1 : A = g_xc,  W = g_wqkvc, epilogue scatters to g_q/g_k/g_v
// EPI == 0 : A = g_att, W = g_woutc, epilogue writes [M,N] to out
// CTA tile 128x128, kTile 16, 8 warps (2x4), 64x32 per warp, m16n8k8 mma.
// ---------------------------------------------------------------------------
#define A_STRIDE 20    // 16 + 4 pad
#define B_STRIDE 132   // 128 + 4 pad

template <int EPI>
__global__ __launch_bounds__(256) void tgemm_kernel(
    const float* __restrict__ bias,
    float* __restrict__ out,
    int M, int N, int K)
{
    __shared__ float As[2][128 * A_STRIDE];
    __shared__ float Bs[2][16 * B_STRIDE];

    const float* A = (EPI == 1) ? g_xc : g_att;
    const float* W = (EPI == 1) ? g_wqkvc : g_woutc;

    const int tid  = threadIdx.x;
    const int bx   = blockIdx.x;     // N tile
    const int by   = blockIdx.y;     // M tile
    const int warp = tid >> 5;
    const int lane = tid & 31;
    const int g    = lane >> 2;      // 0..7
    const int tig  = lane & 3;       // 0..3
    const int wm   = warp >> 2;      // 0..1
    const int wn   = warp & 3;       // 0..3

    const float* Ablk = A + (size_t)(by * 128) * K;
    const float* Wblk = W + bx * 128;

    float acc[4][4][4];
#pragma unroll
    for (int mt = 0; mt < 4; mt++)
#pragma unroll
        for (int nt = 0; nt < 4; nt++)
#pragma unroll
            for (int e = 0; e < 4; e++) acc[mt][nt][e] = 0.0f;

    auto load_stage = [&](int s, int k0) {
#pragma unroll
        for (int i = 0; i < 2; i++) {
            int f   = tid + 256 * i;     // 0..511
            int row = f >> 2;            // 0..127
            int c4  = f & 3;             // 0..3
            cp_async16(smem_u32(&As[s][row * A_STRIDE + c4 * 4]),
                       Ablk + (size_t)row * K + k0 + c4 * 4);
        }
#pragma unroll
        for (int i = 0; i < 2; i++) {
            int f   = tid + 256 * i;
            int row = f >> 5;            // 0..15
            int c4  = f & 31;            // 0..31
            cp_async16(smem_u32(&Bs[s][row * B_STRIDE + c4 * 4]),
                       Wblk + (size_t)(k0 + row) * N + c4 * 4);
        }
        cp_commit();
    };

    load_stage(0, 0);
    int stage = 0;

    for (int k0 = 0; k0 < K; k0 += 16) {
        cp_wait0();
        __syncthreads();
        if (k0 + 16 < K) load_stage(stage ^ 1, k0 + 16);

        const float* as = As[stage];
        const float* bs = Bs[stage];
#pragma unroll
        for (int kk = 0; kk < 2; kk++) {
            uint32_t afr[4][4];
#pragma unroll
            for (int mt = 0; mt < 4; mt++) {
                int r0 = wm * 64 + mt * 16 + g;
                afr[mt][0] = __float_as_uint(as[r0 * A_STRIDE + kk * 8 + tig]);
                afr[mt][1] = __float_as_uint(as[(r0 + 8) * A_STRIDE + kk * 8 + tig]);
                afr[mt][2] = __float_as_uint(as[r0 * A_STRIDE + kk * 8 + tig + 4]);
                afr[mt][3] = __float_as_uint(as[(r0 + 8) * A_STRIDE + kk * 8 + tig + 4]);
            }
            uint32_t bfr[4][2];
#pragma unroll
            for (int nt = 0; nt < 4; nt++) {
                int col = wn * 32 + nt * 8 + g;
                bfr[nt][0] = __float_as_uint(bs[(kk * 8 + tig) * B_STRIDE + col]);
                bfr[nt][1] = __float_as_uint(bs[(kk * 8 + tig + 4) * B_STRIDE + col]);
            }
#pragma unroll
            for (int mt = 0; mt < 4; mt++)
#pragma unroll
                for (int nt = 0; nt < 4; nt++)
                    mma_tf32(acc[mt][nt], afr[mt], bfr[nt]);
        }
        stage ^= 1;
    }

    // Epilogue: c0:(g,2t) c1:(g,2t+1) c2:(g+8,2t) c3:(g+8,2t+1)
#pragma unroll
    for (int mt = 0; mt < 4; mt++) {
#pragma unroll
        for (int nt = 0; nt < 4; nt++) {
#pragma unroll
            for (int e = 0; e < 4; e++) {
                int mrow = by * 128 + wm * 64 + mt * 16 + g + (e >= 2 ? 8 : 0);
                int n    = bx * 128 + wn * 32 + nt * 8 + 2 * tig + (e & 1);
                float val = acc[mt][nt][e] + bias[n];
                if (EPI == 1) {
                    int b   = mrow >> 9;
                    int t   = mrow & 511;
                    int sec = n >> 10;           // uniform per block
                    int c   = n & 1023;
                    int h   = c >> 6;
                    int d   = c & 63;
                    float* dst = (sec == 0) ? g_q : ((sec == 1) ? g_k : g_v);
                    dst[((b * H_ + h) * T_ + t) * D_ + d] = val;
                } else {
                    out[(size_t)mrow * N + n] = val;
                }
            }
        }
    }
}

// ---------------------------------------------------------------------------
// Causal flash attention, fp32, online softmax.
// ---------------------------------------------------------------------------
__global__ __launch_bounds__(64) void attn_kernel()
{
    __shared__ __align__(16) float Ks[64 * 64];
    __shared__ __align__(16) float Vs[64 * 64];
    __shared__ __align__(16) float Qs[64 * 64];

    const int t  = threadIdx.x;
    const int qt = blockIdx.x;
    const int bh = blockIdx.y;
    const int b  = bh >> 4;
    const int h  = bh & 15;

    const float* Qg = g_q + (size_t)bh * T_ * D_;
    const float* Kg = g_k + (size_t)bh * T_ * D_;
    const float* Vg = g_v + (size_t)bh * T_ * D_;

    for (int r = 0; r < 64; r++)
        Qs[r * 64 + ((t + r) & 63)] = Qg[(qt * 64 + r) * 64 + t];
    __syncthreads();

    float q[64];
#pragma unroll
    for (int d = 0; d < 64; d++) q[d] = Qs[t * 64 + ((d + t) & 63)];
    __syncthreads();

    float acc[64];
#pragma unroll
    for (int d = 0; d < 64; d++) acc[d] = 0.0f;
    float m = NEG_BIG;
    float l = 0.0f;

    const int qidx = qt * 64 + t;
    const float scale = 0.125f;

    for (int jt = 0; jt <= qt; jt++) {
        const float4* K4g = (const float4*)(Kg + jt * 64 * 64);
        const float4* V4g = (const float4*)(Vg + jt * 64 * 64);
        float4* K4 = (float4*)Ks;
        float4* V4 = (float4*)Vs;
#pragma unroll
        for (int i = 0; i < 16; i++) {
            K4[t + 64 * i] = K4g[t + 64 * i];
            V4[t + 64 * i] = V4g[t + 64 * i];
        }
        __syncthreads();

        const bool diag = (jt == qt);
        float tm = NEG_BIG;
        for (int j = 0; j < 64; j++) {
            float s = 0.0f;
#pragma unroll
            for (int d = 0; d < 64; d++) s += q[d] * Ks[j * 64 + d];
            s *= scale;
            if (diag && (jt * 64 + j) > qidx) s = NEG_BIG;
            Qs[t * 64 + ((j + t) & 63)] = s;
            tm = fmaxf(tm, s);
        }
        float mnew = fmaxf(m, tm);
        float corr = __expf(m - mnew);
        l *= corr;
#pragma unroll
        for (int d = 0; d < 64; d++) acc[d] *= corr;

        for (int j = 0; j < 64; j++) {
            float p = __expf(Qs[t * 64 + ((j + t) & 63)] - mnew);
            l += p;
#pragma unroll
            for (int d = 0; d < 64; d++) acc[d] += p * Vs[j * 64 + d];
        }
        m = mnew;
        __syncthreads();
    }

    float inv = 1.0f / l;
    float* outp = g_att + ((size_t)(b * T_ + qt * 64 + t)) * C_ + h * D_;
#pragma unroll
    for (int d4 = 0; d4 < 16; d4++) {
        float4 v;
        v.x = to_tf32(acc[d4 * 4 + 0] * inv);
        v.y = to_tf32(acc[d4 * 4 + 1] * inv);
        v.z = to_tf32(acc[d4 * 4 + 2] * inv);
        v.w = to_tf32(acc[d4 * 4 + 3] * inv);
        *(float4*)(outp + d4 * 4) = v;
    }
}

// ---------------------------------------------------------------------------
// Launch
// ---------------------------------------------------------------------------
extern "C" void kernel_launch(void* const* d_in, const int* in_sizes, int n_in,
                              void* d_out, int out_size)
{
    const float* x     = (const float*)d_in[0];
    const float* w_qkv = (const float*)d_in[1];
    const float* b_qkv = (const float*)d_in[2];
    const float* w_out = (const float*)d_in[3];
    const float* b_out = (const float*)d_in[4];
    float* out = (float*)d_out;

    // 0) TF32 rounding of GEMM inputs
    {
        int n4x = (M_TOT * C_) / 4;
        cvt_tf32_kernel<<<(n4x + 255) / 256, 256>>>(x, 0, n4x);
        int n4w = (C_ * N_QKV) / 4;
        cvt_tf32_kernel<<<(n4w + 255) / 256, 256>>>(w_qkv, 1, n4w);
        int n4o = (C_ * C_) / 4;
        cvt_tf32_kernel<<<(n4o + 255) / 256, 256>>>(w_out, 2, n4o);
    }
    // 1) QKV projection + bias -> g_q/g_k/g_v [B,H,T,D]
    {
        dim3 grid(N_QKV / 128, M_TOT / 128);  // (24, 128)
        tgemm_kernel<1><<<grid, 256>>>(b_qkv, nullptr, M_TOT, N_QKV, C_);
    }
    // 2) Causal flash attention -> g_att [B,T,C]
    {
        dim3 grid(T_ / 64, B_ * H_);          // (8, 512)
        attn_kernel<<<grid, 64>>>();
    }
    // 3) Output projection + bias -> d_out
    {
        dim3 grid(C_ / 128, M_TOT / 128);     // (8, 128)
        tgemm_kernel<0><<<grid, 256>>>(b_out, out, M_TOT, C_, C_);
    }
}

// round 5
// speedup vs baseline: 2.6882x; 1.3151x over previous
#include <cuda_runtime.h>
#include <stdint.h>
#include <math.h>

// Problem constants
#define B_    32
#define T_    512
#define C_    1024
#define H_    16
#define D_    64
#define M_TOT (B_ * T_)          // 16384
#define N_QKV (3 * C_)           // 3072
#define NEG_BIG (-1.0e30f)

// Scratch (device globals: no allocations allowed)
__device__ float g_q[B_ * H_ * T_ * D_];    // [B,H,T,D]
__device__ float g_k[B_ * H_ * T_ * D_];
__device__ float g_v[B_ * H_ * T_ * D_];
__device__ float g_att[B_ * T_ * C_];       // [B,T,C] attention out (tf32-rounded)
__device__ float g_xc[M_TOT * C_];          // tf32-rounded x
__device__ float g_wqkvc[C_ * N_QKV];       // tf32-rounded w_qkv
__device__ float g_woutc[C_ * C_];          // tf32-rounded w_out

// ---------------------------------------------------------------------------
// Helpers
// ---------------------------------------------------------------------------
__device__ __forceinline__ uint32_t to_tf32_bits(float x) {
    uint32_t y;
    asm("cvt.rna.tf32.f32 %0, %1;" : "=r"(y) : "f"(x));
    return y;
}
__device__ __forceinline__ float to_tf32(float x) {
    return __uint_as_float(to_tf32_bits(x));
}

__device__ __forceinline__ uint32_t smem_u32(const void* p) {
    return (uint32_t)__cvta_generic_to_shared(p);
}

__device__ __forceinline__ void cp_async16(uint32_t dst, const void* src) {
    asm volatile("cp.async.cg.shared.global [%0], [%1], 16;\n" :: "r"(dst), "l"(src));
}
__device__ __forceinline__ void cp_async4(uint32_t dst, const void* src) {
    asm volatile("cp.async.ca.shared.global [%0], [%1], 4;\n" :: "r"(dst), "l"(src));
}
__device__ __forceinline__ void cp_commit() {
    asm volatile("cp.async.commit_group;\n" ::);
}
__device__ __forceinline__ void cp_wait0() {
    asm volatile("cp.async.wait_group 0;\n" ::);
}

__device__ __forceinline__ void mma_tf32(float* c, const uint32_t* a, const uint32_t* b) {
    asm volatile(
        "mma.sync.aligned.m16n8k8.row.col.f32.tf32.tf32.f32 "
        "{%0,%1,%2,%3}, {%4,%5,%6,%7}, {%8,%9}, {%0,%1,%2,%3};\n"
        : "+f"(c[0]), "+f"(c[1]), "+f"(c[2]), "+f"(c[3])
        : "r"(a[0]), "r"(a[1]), "r"(a[2]), "r"(a[3]),
          "r"(b[0]), "r"(b[1]));
}

// ---------------------------------------------------------------------------
// TF32 round kernel
// ---------------------------------------------------------------------------
__global__ __launch_bounds__(256) void cvt_tf32_kernel(
    const float* __restrict__ in, int sel, int n4)
{
    float* out = (sel == 0) ? g_xc : (sel == 1) ? g_wqkvc : g_woutc;
    int i = blockIdx.x * blockDim.x + threadIdx.x;
    if (i < n4) {
        float4 v = ((const float4*)in)[i];
        v.x = to_tf32(v.x);
        v.y = to_tf32(v.y);
        v.z = to_tf32(v.z);
        v.w = to_tf32(v.w);
        ((float4*)out)[i] = v;
    }
}

// ---------------------------------------------------------------------------
// TF32 tensor-core GEMM: out = A[M,K] @ W[K,N] + bias
// A smem tile stored with permuted columns p(c)=(c&3)*4+(c>>2) so each thread
// fetches its 4 A-fragment values for both k-substeps with one LDS.128.
// ---------------------------------------------------------------------------
#define B_STRIDE 132   // 128 + 4 pad

template <int EPI>
__global__ __launch_bounds__(256) void tgemm_kernel(
    const float* __restrict__ bias,
    float* __restrict__ out,
    int M, int N, int K)
{
    __shared__ float As[2][128 * 16];      // permuted, stride 16 (no pad needed)
    __shared__ float Bs[2][16 * B_STRIDE];

    const float* A = (EPI == 1) ? g_xc : g_att;
    const float* W = (EPI == 1) ? g_wqkvc : g_woutc;

    const int tid  = threadIdx.x;
    const int bx   = blockIdx.x;
    const int by   = blockIdx.y;
    const int warp = tid >> 5;
    const int lane = tid & 31;
    const int g    = lane >> 2;
    const int tig  = lane & 3;
    const int wm   = warp >> 2;
    const int wn   = warp & 3;

    const float* Ablk = A + (size_t)(by * 128) * K;
    const float* Wblk = W + bx * 128;

    float acc[4][4][4];
#pragma unroll
    for (int mt = 0; mt < 4; mt++)
#pragma unroll
        for (int nt = 0; nt < 4; nt++)
#pragma unroll
            for (int e = 0; e < 4; e++) acc[mt][nt][e] = 0.0f;

    auto load_stage = [&](int s, int k0) {
        // A: 2048 scalars, permuted columns. gmem side coalesced (col = f&15).
#pragma unroll
        for (int i = 0; i < 8; i++) {
            int f   = tid + 256 * i;     // 0..2047
            int row = f >> 4;            // 0..127
            int col = f & 15;            // 0..15
            int p   = (col & 3) * 4 + (col >> 2);
            cp_async4(smem_u32(&As[s][row * 16 + p]),
                      Ablk + (size_t)row * K + k0 + col);
        }
#pragma unroll
        for (int i = 0; i < 2; i++) {
            int f   = tid + 256 * i;
            int row = f >> 5;            // 0..15
            int c4  = f & 31;            // 0..31
            cp_async16(smem_u32(&Bs[s][row * B_STRIDE + c4 * 4]),
                       Wblk + (size_t)(k0 + row) * N + c4 * 4);
        }
        cp_commit();
    };

    load_stage(0, 0);
    int stage = 0;

    for (int k0 = 0; k0 < K; k0 += 16) {
        cp_wait0();
        __syncthreads();
        if (k0 + 16 < K) load_stage(stage ^ 1, k0 + 16);

        const float* as = As[stage];
        const float* bs = Bs[stage];

        float4 alo[4], ahi[4];
#pragma unroll
        for (int mt = 0; mt < 4; mt++) {
            int r0 = wm * 64 + mt * 16 + g;
            alo[mt] = *(const float4*)&as[r0 * 16 + tig * 4];
            ahi[mt] = *(const float4*)&as[(r0 + 8) * 16 + tig * 4];
        }
        uint32_t bfr[2][4][2];
#pragma unroll
        for (int kk = 0; kk < 2; kk++)
#pragma unroll
            for (int nt = 0; nt < 4; nt++) {
                int col = wn * 32 + nt * 8 + g;
                bfr[kk][nt][0] = __float_as_uint(bs[(kk * 8 + tig) * B_STRIDE + col]);
                bfr[kk][nt][1] = __float_as_uint(bs[(kk * 8 + tig + 4) * B_STRIDE + col]);
            }
#pragma unroll
        for (int mt = 0; mt < 4; mt++) {
            uint32_t a0[4] = { __float_as_uint(alo[mt].x), __float_as_uint(ahi[mt].x),
                               __float_as_uint(alo[mt].y), __float_as_uint(ahi[mt].y) };
            uint32_t a1[4] = { __float_as_uint(alo[mt].z), __float_as_uint(ahi[mt].z),
                               __float_as_uint(alo[mt].w), __float_as_uint(ahi[mt].w) };
#pragma unroll
            for (int nt = 0; nt < 4; nt++) {
                mma_tf32(acc[mt][nt], a0, bfr[0][nt]);
                mma_tf32(acc[mt][nt], a1, bfr[1][nt]);
            }
        }
        stage ^= 1;
    }

    // Epilogue: c0:(g,2t) c1:(g,2t+1) c2:(g+8,2t) c3:(g+8,2t+1)
#pragma unroll
    for (int mt = 0; mt < 4; mt++) {
#pragma unroll
        for (int nt = 0; nt < 4; nt++) {
#pragma unroll
            for (int e = 0; e < 4; e++) {
                int mrow = by * 128 + wm * 64 + mt * 16 + g + (e >= 2 ? 8 : 0);
                int n    = bx * 128 + wn * 32 + nt * 8 + 2 * tig + (e & 1);
                float val = acc[mt][nt][e] + bias[n];
                if (EPI == 1) {
                    int b   = mrow >> 9;
                    int t   = mrow & 511;
                    int sec = n >> 10;
                    int c   = n & 1023;
                    int h   = c >> 6;
                    int d   = c & 63;
                    float* dst = (sec == 0) ? g_q : ((sec == 1) ? g_k : g_v);
                    dst[((b * H_ + h) * T_ + t) * D_ + d] = val;
                } else {
                    out[(size_t)mrow * N + n] = val;
                }
            }
        }
    }
}

// ---------------------------------------------------------------------------
// TF32 mma causal flash attention.
// CTA: 128 threads (4 warps), 64 query rows per CTA (16 per warp).
// Grid: (T/64, B*H). S and PV via m16n8k8 tf32 mma; FA2 online softmax.
// ---------------------------------------------------------------------------
#define KT_S 68   // K tile row stride (floats): b-load addr 4g+tig -> conflict-free
#define VT_S 72   // V tile row stride: b-load addr 8tig+g -> conflict-free
#define PS_S 68   // P buffer stride: a-load addr 4g+tig -> conflict-free
#define ATTN_SMEM ((64 * KT_S + 64 * VT_S + 64 * PS_S) * 4)

__global__ __launch_bounds__(128) void attn_mma_kernel()
{
    extern __shared__ float sm[];
    float* Kt = sm;                       // [64][KT_S]
    float* Vt = sm + 64 * KT_S;           // [64][VT_S]
    float* Ps = Vt + 64 * VT_S;           // [64][PS_S]

    const int tid  = threadIdx.x;
    const int w    = tid >> 5;
    const int lane = tid & 31;
    const int g    = lane >> 2;
    const int tig  = lane & 3;
    const int qt   = blockIdx.x;
    const int bh   = blockIdx.y;
    const int b    = bh >> 4;
    const int h    = bh & 15;

    const float* Qg = g_q + (size_t)bh * T_ * D_;
    const float* Kg = g_k + (size_t)bh * T_ * D_;
    const float* Vg = g_v + (size_t)bh * T_ * D_;

    const int r0 = qt * 64 + w * 16 + g;   // global q row (lower 8-group)
    const int r1 = r0 + 8;

    // Q fragments, scaled by 1/sqrt(D) and tf32-rounded, held in registers
    uint32_t qa[8][4];
#pragma unroll
    for (int ks = 0; ks < 8; ks++) {
        qa[ks][0] = to_tf32_bits(Qg[r0 * 64 + tig + 8 * ks] * 0.125f);
        qa[ks][1] = to_tf32_bits(Qg[r1 * 64 + tig + 8 * ks] * 0.125f);
        qa[ks][2] = to_tf32_bits(Qg[r0 * 64 + tig + 4 + 8 * ks] * 0.125f);
        qa[ks][3] = to_tf32_bits(Qg[r1 * 64 + tig + 4 + 8 * ks] * 0.125f);
    }

    float oacc[8][4];
#pragma unroll
    for (int nt = 0; nt < 8; nt++)
#pragma unroll
        for (int e = 0; e < 4; e++) oacc[nt][e] = 0.0f;
    float m0 = NEG_BIG, m1 = NEG_BIG, l0 = 0.0f, l1 = 0.0f;

    for (int jt = 0; jt <= qt; jt++) {
        __syncthreads();
        // Stage K/V tile (tf32-rounded). Coalesced float4 gmem reads.
#pragma unroll
        for (int i = 0; i < 8; i++) {
            int f4 = tid + 128 * i;        // 0..1023
            int t  = f4 >> 4;              // 0..63 (tile-local row)
            int j  = f4 & 15;              // float4 col
            float4 kv = *(const float4*)(Kg + (size_t)(jt * 64 + t) * 64 + 4 * j);
            kv.x = to_tf32(kv.x); kv.y = to_tf32(kv.y);
            kv.z = to_tf32(kv.z); kv.w = to_tf32(kv.w);
            *(float4*)(Kt + t * KT_S + 4 * j) = kv;
            float4 vv = *(const float4*)(Vg + (size_t)(jt * 64 + t) * 64 + 4 * j);
            vv.x = to_tf32(vv.x); vv.y = to_tf32(vv.y);
            vv.z = to_tf32(vv.z); vv.w = to_tf32(vv.w);
            *(float4*)(Vt + t * VT_S + 4 * j) = vv;
        }
        __syncthreads();

        // S = Q K^T (16 x 64 per warp)
        float cfr[8][4];
#pragma unroll
        for (int nt = 0; nt < 8; nt++)
#pragma unroll
            for (int e = 0; e < 4; e++) cfr[nt][e] = 0.0f;
#pragma unroll
        for (int ks = 0; ks < 8; ks++) {
#pragma unroll
            for (int nt = 0; nt < 8; nt++) {
                uint32_t bf[2];
                bf[0] = __float_as_uint(Kt[(nt * 8 + g) * KT_S + tig + 8 * ks]);
                bf[1] = __float_as_uint(Kt[(nt * 8 + g) * KT_S + tig + 4 + 8 * ks]);
                mma_tf32(cfr[nt], qa[ks], bf);
            }
        }

        // causal mask on diagonal tile
        if (jt == qt) {
#pragma unroll
            for (int nt = 0; nt < 8; nt++) {
                int jc = jt * 64 + nt * 8 + 2 * tig;
                if (jc     > r0) cfr[nt][0] = NEG_BIG;
                if (jc + 1 > r0) cfr[nt][1] = NEG_BIG;
                if (jc     > r1) cfr[nt][2] = NEG_BIG;
                if (jc + 1 > r1) cfr[nt][3] = NEG_BIG;
            }
        }

        // online softmax
        float mx0 = NEG_BIG, mx1 = NEG_BIG;
#pragma unroll
        for (int nt = 0; nt < 8; nt++) {
            mx0 = fmaxf(mx0, fmaxf(cfr[nt][0], cfr[nt][1]));
            mx1 = fmaxf(mx1, fmaxf(cfr[nt][2], cfr[nt][3]));
        }
        mx0 = fmaxf(mx0, __shfl_xor_sync(0xffffffffu, mx0, 1));
        mx0 = fmaxf(mx0, __shfl_xor_sync(0xffffffffu, mx0, 2));
        mx1 = fmaxf(mx1, __shfl_xor_sync(0xffffffffu, mx1, 1));
        mx1 = fmaxf(mx1, __shfl_xor_sync(0xffffffffu, mx1, 2));
        float mn0 = fmaxf(m0, mx0), mn1 = fmaxf(m1, mx1);
        float cr0 = __expf(m0 - mn0), cr1 = __expf(m1 - mn1);
        l0 *= cr0; l1 *= cr1;
#pragma unroll
        for (int nt = 0; nt < 8; nt++) {
            oacc[nt][0] *= cr0; oacc[nt][1] *= cr0;
            oacc[nt][2] *= cr1; oacc[nt][3] *= cr1;
        }
        const int pr0 = (w * 16 + g) * PS_S;
        const int pr1 = (w * 16 + g + 8) * PS_S;
#pragma unroll
        for (int nt = 0; nt < 8; nt++) {
            int pc = nt * 8 + 2 * tig;
            float p0 = to_tf32(__expf(cfr[nt][0] - mn0));
            float p1 = to_tf32(__expf(cfr[nt][1] - mn0));
            float p2 = to_tf32(__expf(cfr[nt][2] - mn1));
            float p3 = to_tf32(__expf(cfr[nt][3] - mn1));
            l0 += p0 + p1;
            l1 += p2 + p3;
            Ps[pr0 + pc]     = p0;
            Ps[pr0 + pc + 1] = p1;
            Ps[pr1 + pc]     = p2;
            Ps[pr1 + pc + 1] = p3;
        }
        m0 = mn0; m1 = mn1;
        __syncwarp();

        // O += P V
#pragma unroll
        for (int ks = 0; ks < 8; ks++) {
            uint32_t pa[4];
            pa[0] = __float_as_uint(Ps[pr0 + tig + 8 * ks]);
            pa[1] = __float_as_uint(Ps[pr1 + tig + 8 * ks]);
            pa[2] = __float_as_uint(Ps[pr0 + tig + 4 + 8 * ks]);
            pa[3] = __float_as_uint(Ps[pr1 + tig + 4 + 8 * ks]);
#pragma unroll
            for (int nt = 0; nt < 8; nt++) {
                uint32_t bf[2];
                bf[0] = __float_as_uint(Vt[(tig + 8 * ks) * VT_S + nt * 8 + g]);
                bf[1] = __float_as_uint(Vt[(tig + 4 + 8 * ks) * VT_S + nt * 8 + g]);
                mma_tf32(oacc[nt], pa, bf);
            }
        }
        __syncwarp();
    }

    // finalize: reduce l over the tig quad, normalize, write [B,T,C]
    l0 += __shfl_xor_sync(0xffffffffu, l0, 1);
    l0 += __shfl_xor_sync(0xffffffffu, l0, 2);
    l1 += __shfl_xor_sync(0xffffffffu, l1, 1);
    l1 += __shfl_xor_sync(0xffffffffu, l1, 2);
    float i0 = 1.0f / l0, i1 = 1.0f / l1;

    float* out0 = g_att + (size_t)(b * T_ + r0) * C_ + h * 64;
    float* out1 = g_att + (size_t)(b * T_ + r1) * C_ + h * 64;
#pragma unroll
    for (int nt = 0; nt < 8; nt++) {
        int pc = nt * 8 + 2 * tig;
        float2 v0, v1;
        v0.x = to_tf32(oacc[nt][0] * i0);
        v0.y = to_tf32(oacc[nt][1] * i0);
        v1.x = to_tf32(oacc[nt][2] * i1);
        v1.y = to_tf32(oacc[nt][3] * i1);
        *(float2*)(out0 + pc) = v0;
        *(float2*)(out1 + pc) = v1;
    }
}

// ---------------------------------------------------------------------------
// Launch
// ---------------------------------------------------------------------------
extern "C" void kernel_launch(void* const* d_in, const int* in_sizes, int n_in,
                              void* d_out, int out_size)
{
    const float* x     = (const float*)d_in[0];
    const float* w_qkv = (const float*)d_in[1];
    const float* b_qkv = (const float*)d_in[2];
    const float* w_out = (const float*)d_in[3];
    const float* b_out = (const float*)d_in[4];
    float* out = (float*)d_out;

    cudaFuncSetAttribute(attn_mma_kernel,
                         cudaFuncAttributeMaxDynamicSharedMemorySize, ATTN_SMEM);

    // 0) TF32 rounding of GEMM inputs
    {
        int n4x = (M_TOT * C_) / 4;
        cvt_tf32_kernel<<<(n4x + 255) / 256, 256>>>(x, 0, n4x);
        int n4w = (C_ * N_QKV) / 4;
        cvt_tf32_kernel<<<(n4w + 255) / 256, 256>>>(w_qkv, 1, n4w);
        int n4o = (C_ * C_) / 4;
        cvt_tf32_kernel<<<(n4o + 255) / 256, 256>>>(w_out, 2, n4o);
    }
    // 1) QKV projection + bias -> g_q/g_k/g_v [B,H,T,D]
    {
        dim3 grid(N_QKV / 128, M_TOT / 128);  // (24, 128)
        tgemm_kernel<1><<<grid, 256>>>(b_qkv, nullptr, M_TOT, N_QKV, C_);
    }
    // 2) Causal flash attention (tf32 mma) -> g_att [B,T,C]
    {
        dim3 grid(T_ / 64, B_ * H_);          // (8, 512)
        attn_mma_kernel<<<grid, 128, ATTN_SMEM>>>();
    }
    // 3) Output projection + bias -> d_out
    {
        dim3 grid(C_ / 128, M_TOT / 128);     // (8, 128)
        tgemm_kernel<0><<<grid, 256>>>(b_out, out, M_TOT, C_, C_);
    }
}

// round 6
// speedup vs baseline: 3.5688x; 1.3276x over previous
#include <cuda_runtime.h>
#include <stdint.h>
#include <math.h>

// Problem constants
#define B_    32
#define T_    512
#define C_    1024
#define H_    16
#define D_    64
#define M_TOT (B_ * T_)          // 16384
#define N_QKV (3 * C_)           // 3072
#define NEG_BIG (-1.0e30f)

// Scratch (device globals: no allocations allowed)
__device__ float g_q[B_ * H_ * T_ * D_];    // [B,H,T,D]
__device__ float g_k[B_ * H_ * T_ * D_];
__device__ float g_v[B_ * H_ * T_ * D_];
__device__ float g_att[M_TOT * C_];         // [B,T,C], K-block-permuted cols
__device__ float g_xc[M_TOT * C_];          // tf32 x, K-block-permuted cols
__device__ float g_wqkvt[N_QKV * C_];       // tf32 w_qkv^T [N][K], K-perm
__device__ float g_woutt[C_ * C_];          // tf32 w_out^T [N][K], K-perm

// K-block permutation within 16-element blocks: holds columns {t,4+t,8+t,12+t}
// contiguously so one LDS.128 fetches an mma k8-fragment pair.
__device__ __host__ __forceinline__ int kperm(int c) {
    return (c & ~15) | (((c & 3) << 2) | ((c & 15) >> 2));
}

// ---------------------------------------------------------------------------
// Helpers
// ---------------------------------------------------------------------------
__device__ __forceinline__ uint32_t to_tf32_bits(float x) {
    uint32_t y;
    asm("cvt.rna.tf32.f32 %0, %1;" : "=r"(y) : "f"(x));
    return y;
}
__device__ __forceinline__ float to_tf32(float x) {
    return __uint_as_float(to_tf32_bits(x));
}

__device__ __forceinline__ uint32_t smem_u32(const void* p) {
    return (uint32_t)__cvta_generic_to_shared(p);
}
__device__ __forceinline__ void cp_async16(uint32_t dst, const void* src) {
    asm volatile("cp.async.cg.shared.global [%0], [%1], 16;\n" :: "r"(dst), "l"(src));
}
__device__ __forceinline__ void cp_commit() {
    asm volatile("cp.async.commit_group;\n" ::);
}
__device__ __forceinline__ void cp_wait0() {
    asm volatile("cp.async.wait_group 0;\n" ::);
}

__device__ __forceinline__ void mma_tf32(float* c, const uint32_t* a, const uint32_t* b) {
    asm volatile(
        "mma.sync.aligned.m16n8k8.row.col.f32.tf32.tf32.f32 "
        "{%0,%1,%2,%3}, {%4,%5,%6,%7}, {%8,%9}, {%0,%1,%2,%3};\n"
        : "+f"(c[0]), "+f"(c[1]), "+f"(c[2]), "+f"(c[3])
        : "r"(a[0]), "r"(a[1]), "r"(a[2]), "r"(a[3]),
          "r"(b[0]), "r"(b[1]));
}

// ---------------------------------------------------------------------------
// cvt + permute (x -> g_xc): tf32 round, K-block permute columns.
// ---------------------------------------------------------------------------
__global__ __launch_bounds__(256) void cvt_x_kernel(const float* __restrict__ in)
{
    int i = blockIdx.x * blockDim.x + threadIdx.x;   // float4 id
    float4 v = ((const float4*)in)[i];
    int row = i >> 8;                 // C_/4 = 256 float4 per row
    int c   = (i & 255) * 4;          // column of v.x
    float* orow = g_xc + (size_t)row * C_;
    orow[kperm(c + 0)] = to_tf32(v.x);
    orow[kperm(c + 1)] = to_tf32(v.y);
    orow[kperm(c + 2)] = to_tf32(v.z);
    orow[kperm(c + 3)] = to_tf32(v.w);
}

// ---------------------------------------------------------------------------
// cvt + transpose + permute (W[K][N] -> Wt[N][K] K-block-permuted).
// 32x32 tiles, 256 threads.
// ---------------------------------------------------------------------------
__global__ __launch_bounds__(256) void cvt_wt_kernel(
    const float* __restrict__ in, float* __restrict__ outp, int K, int N)
{
    __shared__ float sm[32][33];
    const int tx = threadIdx.x & 31;
    const int ty = threadIdx.x >> 5;       // 0..7
    const int k0 = blockIdx.x * 32;
    const int n0 = blockIdx.y * 32;
#pragma unroll
    for (int i = 0; i < 4; i++) {
        int k = ty + i * 8;
        sm[k][tx] = in[(size_t)(k0 + k) * N + n0 + tx];
    }
    __syncthreads();
#pragma unroll
    for (int i = 0; i < 4; i++) {
        int n = ty + i * 8;
        outp[(size_t)(n0 + n) * K + k0 + kperm(tx)] = to_tf32(sm[tx][n]);
    }
}

// ---------------------------------------------------------------------------
// TF32 tensor-core GEMM: out = A[M,K] @ W[K,N] + bias
// A from K-permuted row-major gmem; W from K-permuted [N][K] gmem.
// Smem: As[128][16], Bs[128][16] per stage. Consumer: LDS.128 only.
// ---------------------------------------------------------------------------
template <int EPI>
__global__ __launch_bounds__(256) void tgemm_kernel(
    const float* __restrict__ Wt,
    const float* __restrict__ bias,
    float* __restrict__ out,
    int M, int N, int K)
{
    __shared__ float As[2][128 * 16];
    __shared__ float Bs[2][128 * 16];

    const float* A = (EPI == 1) ? g_xc : g_att;

    const int tid  = threadIdx.x;
    const int bx   = blockIdx.x;
    const int by   = blockIdx.y;
    const int warp = tid >> 5;
    const int lane = tid & 31;
    const int g    = lane >> 2;
    const int tig  = lane & 3;
    const int wm   = warp >> 2;
    const int wn   = warp & 3;

    const float* Ablk = A + (size_t)(by * 128) * K;
    const float* Wblk = Wt + (size_t)(bx * 128) * K;

    float acc[4][4][4];
#pragma unroll
    for (int mt = 0; mt < 4; mt++)
#pragma unroll
        for (int nt = 0; nt < 4; nt++)
#pragma unroll
            for (int e = 0; e < 4; e++) acc[mt][nt][e] = 0.0f;

    auto load_stage = [&](int s, int k0) {
#pragma unroll
        for (int i = 0; i < 2; i++) {
            int f   = tid + 256 * i;     // 0..511
            int row = f >> 2;            // 0..127
            int c4  = f & 3;             // 0..3
            cp_async16(smem_u32(&As[s][row * 16 + c4 * 4]),
                       Ablk + (size_t)row * K + k0 + c4 * 4);
            cp_async16(smem_u32(&Bs[s][row * 16 + c4 * 4]),
                       Wblk + (size_t)row * K + k0 + c4 * 4);
        }
        cp_commit();
    };

    load_stage(0, 0);
    int stage = 0;

    for (int k0 = 0; k0 < K; k0 += 16) {
        cp_wait0();
        __syncthreads();
        if (k0 + 16 < K) load_stage(stage ^ 1, k0 + 16);

        const float* as = As[stage];
        const float* bs = Bs[stage];

        float4 alo[4], ahi[4];
#pragma unroll
        for (int mt = 0; mt < 4; mt++) {
            int r0 = wm * 64 + mt * 16 + g;
            alo[mt] = *(const float4*)&as[r0 * 16 + tig * 4];
            ahi[mt] = *(const float4*)&as[(r0 + 8) * 16 + tig * 4];
        }
        float4 bv[4];
#pragma unroll
        for (int nt = 0; nt < 4; nt++) {
            int col = wn * 32 + nt * 8 + g;
            bv[nt] = *(const float4*)&bs[col * 16 + tig * 4];
        }
#pragma unroll
        for (int mt = 0; mt < 4; mt++) {
            uint32_t a0[4] = { __float_as_uint(alo[mt].x), __float_as_uint(ahi[mt].x),
                               __float_as_uint(alo[mt].y), __float_as_uint(ahi[mt].y) };
            uint32_t a1[4] = { __float_as_uint(alo[mt].z), __float_as_uint(ahi[mt].z),
                               __float_as_uint(alo[mt].w), __float_as_uint(ahi[mt].w) };
#pragma unroll
            for (int nt = 0; nt < 4; nt++) {
                uint32_t b0[2] = { __float_as_uint(bv[nt].x), __float_as_uint(bv[nt].y) };
                uint32_t b1[2] = { __float_as_uint(bv[nt].z), __float_as_uint(bv[nt].w) };
                mma_tf32(acc[mt][nt], a0, b0);
                mma_tf32(acc[mt][nt], a1, b1);
            }
        }
        stage ^= 1;
    }

    // Epilogue
#pragma unroll
    for (int mt = 0; mt < 4; mt++) {
#pragma unroll
        for (int nt = 0; nt < 4; nt++) {
#pragma unroll
            for (int e = 0; e < 4; e++) {
                int mrow = by * 128 + wm * 64 + mt * 16 + g + (e >= 2 ? 8 : 0);
                int n    = bx * 128 + wn * 32 + nt * 8 + 2 * tig + (e & 1);
                float val = acc[mt][nt][e] + bias[n];
                if (EPI == 1) {
                    int b   = mrow >> 9;
                    int t   = mrow & 511;
                    int sec = n >> 10;
                    int c   = n & 1023;
                    int h   = c >> 6;
                    int d   = c & 63;
                    float* dst = (sec == 0) ? g_q : ((sec == 1) ? g_k : g_v);
                    dst[((b * H_ + h) * T_ + t) * D_ + d] = val;
                } else {
                    out[(size_t)mrow * N + n] = val;
                }
            }
        }
    }
}

// ---------------------------------------------------------------------------
// TF32 mma causal flash attention (as R5), epilogue writes K-permuted g_att.
// ---------------------------------------------------------------------------
#define KT_S 68
#define VT_S 72
#define PS_S 68
#define ATTN_SMEM ((64 * KT_S + 64 * VT_S + 64 * PS_S) * 4)

__global__ __launch_bounds__(128) void attn_mma_kernel()
{
    extern __shared__ float sm[];
    float* Kt = sm;
    float* Vt = sm + 64 * KT_S;
    float* Ps = Vt + 64 * VT_S;

    const int tid  = threadIdx.x;
    const int w    = tid >> 5;
    const int lane = tid & 31;
    const int g    = lane >> 2;
    const int tig  = lane & 3;
    const int qt   = blockIdx.x;
    const int bh   = blockIdx.y;
    const int b    = bh >> 4;
    const int h    = bh & 15;

    const float* Qg = g_q + (size_t)bh * T_ * D_;
    const float* Kg = g_k + (size_t)bh * T_ * D_;
    const float* Vg = g_v + (size_t)bh * T_ * D_;

    const int r0 = qt * 64 + w * 16 + g;
    const int r1 = r0 + 8;

    uint32_t qa[8][4];
#pragma unroll
    for (int ks = 0; ks < 8; ks++) {
        qa[ks][0] = to_tf32_bits(Qg[r0 * 64 + tig + 8 * ks] * 0.125f);
        qa[ks][1] = to_tf32_bits(Qg[r1 * 64 + tig + 8 * ks] * 0.125f);
        qa[ks][2] = to_tf32_bits(Qg[r0 * 64 + tig + 4 + 8 * ks] * 0.125f);
        qa[ks][3] = to_tf32_bits(Qg[r1 * 64 + tig + 4 + 8 * ks] * 0.125f);
    }

    float oacc[8][4];
#pragma unroll
    for (int nt = 0; nt < 8; nt++)
#pragma unroll
        for (int e = 0; e < 4; e++) oacc[nt][e] = 0.0f;
    float m0 = NEG_BIG, m1 = NEG_BIG, l0 = 0.0f, l1 = 0.0f;

    for (int jt = 0; jt <= qt; jt++) {
        __syncthreads();
#pragma unroll
        for (int i = 0; i < 8; i++) {
            int f4 = tid + 128 * i;
            int t  = f4 >> 4;
            int j  = f4 & 15;
            float4 kv = *(const float4*)(Kg + (size_t)(jt * 64 + t) * 64 + 4 * j);
            kv.x = to_tf32(kv.x); kv.y = to_tf32(kv.y);
            kv.z = to_tf32(kv.z); kv.w = to_tf32(kv.w);
            *(float4*)(Kt + t * KT_S + 4 * j) = kv;
            float4 vv = *(const float4*)(Vg + (size_t)(jt * 64 + t) * 64 + 4 * j);
            vv.x = to_tf32(vv.x); vv.y = to_tf32(vv.y);
            vv.z = to_tf32(vv.z); vv.w = to_tf32(vv.w);
            *(float4*)(Vt + t * VT_S + 4 * j) = vv;
        }
        __syncthreads();

        float cfr[8][4];
#pragma unroll
        for (int nt = 0; nt < 8; nt++)
#pragma unroll
            for (int e = 0; e < 4; e++) cfr[nt][e] = 0.0f;
#pragma unroll
        for (int ks = 0; ks < 8; ks++) {
#pragma unroll
            for (int nt = 0; nt < 8; nt++) {
                uint32_t bf[2];
                bf[0] = __float_as_uint(Kt[(nt * 8 + g) * KT_S + tig + 8 * ks]);
                bf[1] = __float_as_uint(Kt[(nt * 8 + g) * KT_S + tig + 4 + 8 * ks]);
                mma_tf32(cfr[nt], qa[ks], bf);
            }
        }

        if (jt == qt) {
#pragma unroll
            for (int nt = 0; nt < 8; nt++) {
                int jc = jt * 64 + nt * 8 + 2 * tig;
                if (jc     > r0) cfr[nt][0] = NEG_BIG;
                if (jc + 1 > r0) cfr[nt][1] = NEG_BIG;
                if (jc     > r1) cfr[nt][2] = NEG_BIG;
                if (jc + 1 > r1) cfr[nt][3] = NEG_BIG;
            }
        }

        float mx0 = NEG_BIG, mx1 = NEG_BIG;
#pragma unroll
        for (int nt = 0; nt < 8; nt++) {
            mx0 = fmaxf(mx0, fmaxf(cfr[nt][0], cfr[nt][1]));
            mx1 = fmaxf(mx1, fmaxf(cfr[nt][2], cfr[nt][3]));
        }
        mx0 = fmaxf(mx0, __shfl_xor_sync(0xffffffffu, mx0, 1));
        mx0 = fmaxf(mx0, __shfl_xor_sync(0xffffffffu, mx0, 2));
        mx1 = fmaxf(mx1, __shfl_xor_sync(0xffffffffu, mx1, 1));
        mx1 = fmaxf(mx1, __shfl_xor_sync(0xffffffffu, mx1, 2));
        float mn0 = fmaxf(m0, mx0), mn1 = fmaxf(m1, mx1);
        float cr0 = __expf(m0 - mn0), cr1 = __expf(m1 - mn1);
        l0 *= cr0; l1 *= cr1;
#pragma unroll
        for (int nt = 0; nt < 8; nt++) {
            oacc[nt][0] *= cr0; oacc[nt][1] *= cr0;
            oacc[nt][2] *= cr1; oacc[nt][3] *= cr1;
        }
        const int pr0 = (w * 16 + g) * PS_S;
        const int pr1 = (w * 16 + g + 8) * PS_S;
#pragma unroll
        for (int nt = 0; nt < 8; nt++) {
            int pc = nt * 8 + 2 * tig;
            float p0 = to_tf32(__expf(cfr[nt][0] - mn0));
            float p1 = to_tf32(__expf(cfr[nt][1] - mn0));
            float p2 = to_tf32(__expf(cfr[nt][2] - mn1));
            float p3 = to_tf32(__expf(cfr[nt][3] - mn1));
            l0 += p0 + p1;
            l1 += p2 + p3;
            Ps[pr0 + pc]     = p0;
            Ps[pr0 + pc + 1] = p1;
            Ps[pr1 + pc]     = p2;
            Ps[pr1 + pc + 1] = p3;
        }
        m0 = mn0; m1 = mn1;
        __syncwarp();

#pragma unroll
        for (int ks = 0; ks < 8; ks++) {
            uint32_t pa[4];
            pa[0] = __float_as_uint(Ps[pr0 + tig + 8 * ks]);
            pa[1] = __float_as_uint(Ps[pr1 + tig + 8 * ks]);
            pa[2] = __float_as_uint(Ps[pr0 + tig + 4 + 8 * ks]);
            pa[3] = __float_as_uint(Ps[pr1 + tig + 4 + 8 * ks]);
#pragma unroll
            for (int nt = 0; nt < 8; nt++) {
                uint32_t bf[2];
                bf[0] = __float_as_uint(Vt[(tig + 8 * ks) * VT_S + nt * 8 + g]);
                bf[1] = __float_as_uint(Vt[(tig + 4 + 8 * ks) * VT_S + nt * 8 + g]);
                mma_tf32(oacc[nt], pa, bf);
            }
        }
        __syncwarp();
    }

    l0 += __shfl_xor_sync(0xffffffffu, l0, 1);
    l0 += __shfl_xor_sync(0xffffffffu, l0, 2);
    l1 += __shfl_xor_sync(0xffffffffu, l1, 1);
    l1 += __shfl_xor_sync(0xffffffffu, l1, 2);
    float i0 = 1.0f / l0, i1 = 1.0f / l1;

    // write K-block-permuted so out-proj GEMM can read A fragments vectorized
    float* out0 = g_att + (size_t)(b * T_ + r0) * C_ + h * 64;
    float* out1 = g_att + (size_t)(b * T_ + r1) * C_ + h * 64;
#pragma unroll
    for (int nt = 0; nt < 8; nt++) {
        int pc = nt * 8 + 2 * tig;
        out0[kperm(pc)]     = to_tf32(oacc[nt][0] * i0);
        out0[kperm(pc + 1)] = to_tf32(oacc[nt][1] * i0);
        out1[kperm(pc)]     = to_tf32(oacc[nt][2] * i1);
        out1[kperm(pc + 1)] = to_tf32(oacc[nt][3] * i1);
    }
}

// ---------------------------------------------------------------------------
// Launch
// ---------------------------------------------------------------------------
extern "C" void kernel_launch(void* const* d_in, const int* in_sizes, int n_in,
                              void* d_out, int out_size)
{
    const float* x     = (const float*)d_in[0];
    const float* w_qkv = (const float*)d_in[1];
    const float* b_qkv = (const float*)d_in[2];
    const float* w_out = (const float*)d_in[3];
    const float* b_out = (const float*)d_in[4];
    float* out = (float*)d_out;

    cudaFuncSetAttribute(attn_mma_kernel,
                         cudaFuncAttributeMaxDynamicSharedMemorySize, ATTN_SMEM);

    // 0) tf32 + permute/transpose prep
    {
        int n4x = (M_TOT * C_) / 4;
        cvt_x_kernel<<<n4x / 256, 256>>>(x);
        float* wqkvt; cudaGetSymbolAddress((void**)&wqkvt, g_wqkvt);
        float* woutt; cudaGetSymbolAddress((void**)&woutt, g_woutt);
        dim3 g1(C_ / 32, N_QKV / 32);
        cvt_wt_kernel<<<g1, 256>>>(w_qkv, wqkvt, C_, N_QKV);
        dim3 g2(C_ / 32, C_ / 32);
        cvt_wt_kernel<<<g2, 256>>>(w_out, woutt, C_, C_);
    }
    // 1) QKV projection + bias -> g_q/g_k/g_v [B,H,T,D]
    {
        float* wqkvt; cudaGetSymbolAddress((void**)&wqkvt, g_wqkvt);
        dim3 grid(N_QKV / 128, M_TOT / 128);  // (24, 128)
        tgemm_kernel<1><<<grid, 256>>>(wqkvt, b_qkv, nullptr, M_TOT, N_QKV, C_);
    }
    // 2) Causal flash attention (tf32 mma) -> g_att (K-permuted)
    {
        dim3 grid(T_ / 64, B_ * H_);          // (8, 512)
        attn_mma_kernel<<<grid, 128, ATTN_SMEM>>>();
    }
    // 3) Output projection + bias -> d_out
    {
        float* woutt; cudaGetSymbolAddress((void**)&woutt, g_woutt);
        dim3 grid(C_ / 128, M_TOT / 128);     // (8, 128)
        tgemm_kernel<0><<<grid, 256>>>(woutt, b_out, out, M_TOT, C_, C_);
    }
}

// round 8
// speedup vs baseline: 3.7714x; 1.0568x over previous
#include <cuda_runtime.h>
#include <stdint.h>
#include <math.h>

// Problem constants
#define B_    32
#define T_    512
#define C_    1024
#define H_    16
#define D_    64
#define M_TOT (B_ * T_)          // 16384
#define N_QKV (3 * C_)           // 3072
#define NEG_BIG (-1.0e30f)

// Scratch (device globals: no allocations allowed)
__device__ float g_q[B_ * H_ * T_ * D_];    // [B,H,T,D]
__device__ float g_k[B_ * H_ * T_ * D_];
__device__ float g_v[B_ * H_ * T_ * D_];
__device__ float g_att[M_TOT * C_];         // [B,T,C], K-block-permuted cols
__device__ float g_xc[M_TOT * C_];          // tf32 x, K-block-permuted cols
__device__ float g_wqkvt[N_QKV * C_];       // tf32 w_qkv^T [N][K], K-perm
__device__ float g_woutt[C_ * C_];          // tf32 w_out^T [N][K], K-perm

// K-block permutation within 16-element blocks: position 4t+j holds original
// column 4j+t, so one LDS.128 at 4*tig fetches cols {tig,4+tig,8+tig,12+tig}.
__device__ __host__ __forceinline__ int kperm(int c) {
    return (c & ~15) | (((c & 3) << 2) | ((c & 15) >> 2));
}

// ---------------------------------------------------------------------------
// Helpers
// ---------------------------------------------------------------------------
__device__ __forceinline__ uint32_t to_tf32_bits(float x) {
    uint32_t y;
    asm("cvt.rna.tf32.f32 %0, %1;" : "=r"(y) : "f"(x));
    return y;
}
__device__ __forceinline__ float to_tf32(float x) {
    return __uint_as_float(to_tf32_bits(x));
}

__device__ __forceinline__ uint32_t smem_u32(const void* p) {
    return (uint32_t)__cvta_generic_to_shared(p);
}
__device__ __forceinline__ void cp_async16(uint32_t dst, const void* src) {
    asm volatile("cp.async.cg.shared.global [%0], [%1], 16;\n" :: "r"(dst), "l"(src));
}
__device__ __forceinline__ void cp_commit() {
    asm volatile("cp.async.commit_group;\n" ::);
}
__device__ __forceinline__ void cp_wait0() {
    asm volatile("cp.async.wait_group 0;\n" ::);
}

__device__ __forceinline__ void mma_tf32(float* c, const uint32_t* a, const uint32_t* b) {
    asm volatile(
        "mma.sync.aligned.m16n8k8.row.col.f32.tf32.tf32.f32 "
        "{%0,%1,%2,%3}, {%4,%5,%6,%7}, {%8,%9}, {%0,%1,%2,%3};\n"
        : "+f"(c[0]), "+f"(c[1]), "+f"(c[2]), "+f"(c[3])
        : "r"(a[0]), "r"(a[1]), "r"(a[2]), "r"(a[3]),
          "r"(b[0]), "r"(b[1]));
}

// ---------------------------------------------------------------------------
// cvt + permute (x -> g_xc)
// ---------------------------------------------------------------------------
__global__ __launch_bounds__(256) void cvt_x_kernel(const float* __restrict__ in)
{
    int i = blockIdx.x * blockDim.x + threadIdx.x;   // float4 id
    float4 v = ((const float4*)in)[i];
    int row = i >> 8;
    int c   = (i & 255) * 4;
    float* orow = g_xc + (size_t)row * C_;
    orow[kperm(c + 0)] = to_tf32(v.x);
    orow[kperm(c + 1)] = to_tf32(v.y);
    orow[kperm(c + 2)] = to_tf32(v.z);
    orow[kperm(c + 3)] = to_tf32(v.w);
}

// ---------------------------------------------------------------------------
// cvt + transpose + permute (W[K][N] -> Wt[N][K] K-block-permuted)
// ---------------------------------------------------------------------------
__global__ __launch_bounds__(256) void cvt_wt_kernel(
    const float* __restrict__ in, float* __restrict__ outp, int K, int N)
{
    __shared__ float sm[32][33];
    const int tx = threadIdx.x & 31;
    const int ty = threadIdx.x >> 5;
    const int k0 = blockIdx.x * 32;
    const int n0 = blockIdx.y * 32;
#pragma unroll
    for (int i = 0; i < 4; i++) {
        int k = ty + i * 8;
        sm[k][tx] = in[(size_t)(k0 + k) * N + n0 + tx];
    }
    __syncthreads();
#pragma unroll
    for (int i = 0; i < 4; i++) {
        int n = ty + i * 8;
        outp[(size_t)(n0 + n) * K + k0 + kperm(tx)] = to_tf32(sm[tx][n]);
    }
}

// ---------------------------------------------------------------------------
// TF32 tensor-core GEMM (compile-time N,K): out = A[M,K] @ Wt[N,K]^T + bias
// kTile=32, 2-stage cp.async pipeline, dynamic smem, stride-48 rows
// (48 = 16 mod 32 -> every LDS.128 8-lane phase is bank-conflict-free).
// ---------------------------------------------------------------------------
#define SROW 48
#define STG  (128 * SROW)                 // floats per stage per array
#define GEMM_SMEM (4 * STG * 4)           // bytes: 2 stages x (A + B)

template <int EPI, int N, int K>
__global__ __launch_bounds__(256, 2) void tgemm_kernel(
    const float* __restrict__ Wt,
    const float* __restrict__ bias,
    float* __restrict__ out)
{
    extern __shared__ float smem[];
    float* As = smem;            // [2][STG]
    float* Bs = smem + 2 * STG;  // [2][STG]

    const float* A = (EPI == 1) ? g_xc : g_att;

    const int tid  = threadIdx.x;
    const int bx   = blockIdx.x;
    const int by   = blockIdx.y;
    const int warp = tid >> 5;
    const int lane = tid & 31;
    const int g    = lane >> 2;
    const int tig  = lane & 3;
    const int wm   = warp >> 2;
    const int wn   = warp & 3;

    // producer: thread handles rows (tid>>3)+32i, float4 col (tid&7)
    const int prow = tid >> 3;
    const int pc4  = (tid & 7) * 4;
    const float* ag = A  + ((size_t)(by * 128 + prow)) * K + pc4;
    const float* bg = Wt + ((size_t)(bx * 128 + prow)) * K + pc4;
    const uint32_t a_dst = smem_u32(&As[prow * SROW + pc4]);
    const uint32_t b_dst = smem_u32(&Bs[prow * SROW + pc4]);

    float acc[4][4][4];
#pragma unroll
    for (int mt = 0; mt < 4; mt++)
#pragma unroll
        for (int nt = 0; nt < 4; nt++)
#pragma unroll
            for (int e = 0; e < 4; e++) acc[mt][nt][e] = 0.0f;

    auto load_stage = [&](int s, int k0) {
        const uint32_t sb = (uint32_t)(s * STG * 4);
#pragma unroll
        for (int i = 0; i < 4; i++) {
            cp_async16(a_dst + sb + i * (32 * SROW * 4), ag + k0 + i * (32 * K));
            cp_async16(b_dst + sb + i * (32 * SROW * 4), bg + k0 + i * (32 * K));
        }
        cp_commit();
    };

    load_stage(0, 0);
    int stage = 0;

#pragma unroll 1
    for (int k0 = 0; k0 < K; k0 += 32) {
        cp_wait0();
        __syncthreads();
        if (k0 + 32 < K) load_stage(stage ^ 1, k0 + 32);

        const float* as = As + stage * STG;
        const float* bs = Bs + stage * STG;

#pragma unroll
        for (int kc = 0; kc < 2; kc++) {
            const int kb = kc * 16;
            float4 alo[4], ahi[4];
#pragma unroll
            for (int mt = 0; mt < 4; mt++) {
                int r0 = wm * 64 + mt * 16 + g;
                alo[mt] = *(const float4*)&as[r0 * SROW + kb + tig * 4];
                ahi[mt] = *(const float4*)&as[(r0 + 8) * SROW + kb + tig * 4];
            }
            float4 bv[4];
#pragma unroll
            for (int nt = 0; nt < 4; nt++) {
                int col = wn * 32 + nt * 8 + g;
                bv[nt] = *(const float4*)&bs[col * SROW + kb + tig * 4];
            }
#pragma unroll
            for (int mt = 0; mt < 4; mt++) {
                uint32_t a0[4] = { __float_as_uint(alo[mt].x), __float_as_uint(ahi[mt].x),
                                   __float_as_uint(alo[mt].y), __float_as_uint(ahi[mt].y) };
                uint32_t a1[4] = { __float_as_uint(alo[mt].z), __float_as_uint(ahi[mt].z),
                                   __float_as_uint(alo[mt].w), __float_as_uint(ahi[mt].w) };
#pragma unroll
                for (int nt = 0; nt < 4; nt++) {
                    uint32_t b0[2] = { __float_as_uint(bv[nt].x), __float_as_uint(bv[nt].y) };
                    uint32_t b1[2] = { __float_as_uint(bv[nt].z), __float_as_uint(bv[nt].w) };
                    mma_tf32(acc[mt][nt], a0, b0);
                    mma_tf32(acc[mt][nt], a1, b1);
                }
            }
        }
        stage ^= 1;
    }

    // Epilogue
#pragma unroll
    for (int mt = 0; mt < 4; mt++) {
#pragma unroll
        for (int nt = 0; nt < 4; nt++) {
#pragma unroll
            for (int e = 0; e < 4; e++) {
                int mrow = by * 128 + wm * 64 + mt * 16 + g + (e >= 2 ? 8 : 0);
                int n    = bx * 128 + wn * 32 + nt * 8 + 2 * tig + (e & 1);
                float val = acc[mt][nt][e] + bias[n];
                if (EPI == 1) {
                    int b   = mrow >> 9;
                    int t   = mrow & 511;
                    int sec = n >> 10;
                    int c   = n & 1023;
                    int h   = c >> 6;
                    int d   = c & 63;
                    float* dst = (sec == 0) ? g_q : ((sec == 1) ? g_k : g_v);
                    dst[((b * H_ + h) * T_ + t) * D_ + d] = val;
                } else {
                    out[(size_t)mrow * N + n] = val;
                }
            }
        }
    }
}

// ---------------------------------------------------------------------------
// TF32 mma causal flash attention; epilogue writes K-permuted g_att.
// ---------------------------------------------------------------------------
#define KT_S 68
#define VT_S 72
#define PS_S 68
#define ATTN_SMEM ((64 * KT_S + 64 * VT_S + 64 * PS_S) * 4)

__global__ __launch_bounds__(128) void attn_mma_kernel()
{
    extern __shared__ float sm[];
    float* Kt = sm;
    float* Vt = sm + 64 * KT_S;
    float* Ps = Vt + 64 * VT_S;

    const int tid  = threadIdx.x;
    const int w    = tid >> 5;
    const int lane = tid & 31;
    const int g    = lane >> 2;
    const int tig  = lane & 3;
    const int qt   = blockIdx.x;
    const int bh   = blockIdx.y;
    const int b    = bh >> 4;
    const int h    = bh & 15;

    const float* Qg = g_q + (size_t)bh * T_ * D_;
    const float* Kg = g_k + (size_t)bh * T_ * D_;
    const float* Vg = g_v + (size_t)bh * T_ * D_;

    const int r0 = qt * 64 + w * 16 + g;
    const int r1 = r0 + 8;

    uint32_t qa[8][4];
#pragma unroll
    for (int ks = 0; ks < 8; ks++) {
        qa[ks][0] = to_tf32_bits(Qg[r0 * 64 + tig + 8 * ks] * 0.125f);
        qa[ks][1] = to_tf32_bits(Qg[r1 * 64 + tig + 8 * ks] * 0.125f);
        qa[ks][2] = to_tf32_bits(Qg[r0 * 64 + tig + 4 + 8 * ks] * 0.125f);
        qa[ks][3] = to_tf32_bits(Qg[r1 * 64 + tig + 4 + 8 * ks] * 0.125f);
    }

    float oacc[8][4];
#pragma unroll
    for (int nt = 0; nt < 8; nt++)
#pragma unroll
        for (int e = 0; e < 4; e++) oacc[nt][e] = 0.0f;
    float m0 = NEG_BIG, m1 = NEG_BIG, l0 = 0.0f, l1 = 0.0f;

    for (int jt = 0; jt <= qt; jt++) {
        __syncthreads();
#pragma unroll
        for (int i = 0; i < 8; i++) {
            int f4 = tid + 128 * i;
            int t  = f4 >> 4;
            int j  = f4 & 15;
            float4 kv = *(const float4*)(Kg + (size_t)(jt * 64 + t) * 64 + 4 * j);
            kv.x = to_tf32(kv.x); kv.y = to_tf32(kv.y);
            kv.z = to_tf32(kv.z); kv.w = to_tf32(kv.w);
            *(float4*)(Kt + t * KT_S + 4 * j) = kv;
            float4 vv = *(const float4*)(Vg + (size_t)(jt * 64 + t) * 64 + 4 * j);
            vv.x = to_tf32(vv.x); vv.y = to_tf32(vv.y);
            vv.z = to_tf32(vv.z); vv.w = to_tf32(vv.w);
            *(float4*)(Vt + t * VT_S + 4 * j) = vv;
        }
        __syncthreads();

        float cfr[8][4];
#pragma unroll
        for (int nt = 0; nt < 8; nt++)
#pragma unroll
            for (int e = 0; e < 4; e++) cfr[nt][e] = 0.0f;
#pragma unroll
        for (int ks = 0; ks < 8; ks++) {
#pragma unroll
            for (int nt = 0; nt < 8; nt++) {
                uint32_t bf[2];
                bf[0] = __float_as_uint(Kt[(nt * 8 + g) * KT_S + tig + 8 * ks]);
                bf[1] = __float_as_uint(Kt[(nt * 8 + g) * KT_S + tig + 4 + 8 * ks]);
                mma_tf32(cfr[nt], qa[ks], bf);
            }
        }

        if (jt == qt) {
#pragma unroll
            for (int nt = 0; nt < 8; nt++) {
                int jc = jt * 64 + nt * 8 + 2 * tig;
                if (jc     > r0) cfr[nt][0] = NEG_BIG;
                if (jc + 1 > r0) cfr[nt][1] = NEG_BIG;
                if (jc     > r1) cfr[nt][2] = NEG_BIG;
                if (jc + 1 > r1) cfr[nt][3] = NEG_BIG;
            }
        }

        float mx0 = NEG_BIG, mx1 = NEG_BIG;
#pragma unroll
        for (int nt = 0; nt < 8; nt++) {
            mx0 = fmaxf(mx0, fmaxf(cfr[nt][0], cfr[nt][1]));
            mx1 = fmaxf(mx1, fmaxf(cfr[nt][2], cfr[nt][3]));
        }
        mx0 = fmaxf(mx0, __shfl_xor_sync(0xffffffffu, mx0, 1));
        mx0 = fmaxf(mx0, __shfl_xor_sync(0xffffffffu, mx0, 2));
        mx1 = fmaxf(mx1, __shfl_xor_sync(0xffffffffu, mx1, 1));
        mx1 = fmaxf(mx1, __shfl_xor_sync(0xffffffffu, mx1, 2));
        float mn0 = fmaxf(m0, mx0), mn1 = fmaxf(m1, mx1);
        float cr0 = __expf(m0 - mn0), cr1 = __expf(m1 - mn1);
        l0 *= cr0; l1 *= cr1;
#pragma unroll
        for (int nt = 0; nt < 8; nt++) {
            oacc[nt][0] *= cr0; oacc[nt][1] *= cr0;
            oacc[nt][2] *= cr1; oacc[nt][3] *= cr1;
        }
        const int pr0 = (w * 16 + g) * PS_S;
        const int pr1 = (w * 16 + g + 8) * PS_S;
#pragma unroll
        for (int nt = 0; nt < 8; nt++) {
            int pc = nt * 8 + 2 * tig;
            float p0 = to_tf32(__expf(cfr[nt][0] - mn0));
            float p1 = to_tf32(__expf(cfr[nt][1] - mn0));
            float p2 = to_tf32(__expf(cfr[nt][2] - mn1));
            float p3 = to_tf32(__expf(cfr[nt][3] - mn1));
            l0 += p0 + p1;
            l1 += p2 + p3;
            Ps[pr0 + pc]     = p0;
            Ps[pr0 + pc + 1] = p1;
            Ps[pr1 + pc]     = p2;
            Ps[pr1 + pc + 1] = p3;
        }
        m0 = mn0; m1 = mn1;
        __syncwarp();

#pragma unroll
        for (int ks = 0; ks < 8; ks++) {
            uint32_t pa[4];
            pa[0] = __float_as_uint(Ps[pr0 + tig + 8 * ks]);
            pa[1] = __float_as_uint(Ps[pr1 + tig + 8 * ks]);
            pa[2] = __float_as_uint(Ps[pr0 + tig + 4 + 8 * ks]);
            pa[3] = __float_as_uint(Ps[pr1 + tig + 4 + 8 * ks]);
#pragma unroll
            for (int nt = 0; nt < 8; nt++) {
                uint32_t bf[2];
                bf[0] = __float_as_uint(Vt[(tig + 8 * ks) * VT_S + nt * 8 + g]);
                bf[1] = __float_as_uint(Vt[(tig + 4 + 8 * ks) * VT_S + nt * 8 + g]);
                mma_tf32(oacc[nt], pa, bf);
            }
        }
        __syncwarp();
    }

    l0 += __shfl_xor_sync(0xffffffffu, l0, 1);
    l0 += __shfl_xor_sync(0xffffffffu, l0, 2);
    l1 += __shfl_xor_sync(0xffffffffu, l1, 1);
    l1 += __shfl_xor_sync(0xffffffffu, l1, 2);
    float i0 = 1.0f / l0, i1 = 1.0f / l1;

    float* out0 = g_att + (size_t)(b * T_ + r0) * C_ + h * 64;
    float* out1 = g_att + (size_t)(b * T_ + r1) * C_ + h * 64;
#pragma unroll
    for (int nt = 0; nt < 8; nt++) {
        int pc = nt * 8 + 2 * tig;
        out0[kperm(pc)]     = to_tf32(oacc[nt][0] * i0);
        out0[kperm(pc + 1)] = to_tf32(oacc[nt][1] * i0);
        out1[kperm(pc)]     = to_tf32(oacc[nt][2] * i1);
        out1[kperm(pc + 1)] = to_tf32(oacc[nt][3] * i1);
    }
}

// ---------------------------------------------------------------------------
// Launch
// ---------------------------------------------------------------------------
extern "C" void kernel_launch(void* const* d_in, const int* in_sizes, int n_in,
                              void* d_out, int out_size)
{
    const float* x     = (const float*)d_in[0];
    const float* w_qkv = (const float*)d_in[1];
    const float* b_qkv = (const float*)d_in[2];
    const float* w_out = (const float*)d_in[3];
    const float* b_out = (const float*)d_in[4];
    float* out = (float*)d_out;

    cudaFuncSetAttribute(attn_mma_kernel,
                         cudaFuncAttributeMaxDynamicSharedMemorySize, ATTN_SMEM);
    cudaFuncSetAttribute(tgemm_kernel<1, N_QKV, C_>,
                         cudaFuncAttributeMaxDynamicSharedMemorySize, GEMM_SMEM);
    cudaFuncSetAttribute(tgemm_kernel<0, C_, C_>,
                         cudaFuncAttributeMaxDynamicSharedMemorySize, GEMM_SMEM);

    // 0) tf32 + permute/transpose prep
    {
        int n4x = (M_TOT * C_) / 4;
        cvt_x_kernel<<<n4x / 256, 256>>>(x);
        float* wqkvt; cudaGetSymbolAddress((void**)&wqkvt, g_wqkvt);
        float* woutt; cudaGetSymbolAddress((void**)&woutt, g_woutt);
        dim3 g1(C_ / 32, N_QKV / 32);
        cvt_wt_kernel<<<g1, 256>>>(w_qkv, wqkvt, C_, N_QKV);
        dim3 g2(C_ / 32, C_ / 32);
        cvt_wt_kernel<<<g2, 256>>>(w_out, woutt, C_, C_);
    }
    // 1) QKV projection + bias -> g_q/g_k/g_v [B,H,T,D]
    {
        float* wqkvt; cudaGetSymbolAddress((void**)&wqkvt, g_wqkvt);
        dim3 grid(N_QKV / 128, M_TOT / 128);  // (24, 128)
        tgemm_kernel<1, N_QKV, C_><<<grid, 256, GEMM_SMEM>>>(wqkvt, b_qkv, nullptr);
    }
    // 2) Causal flash attention (tf32 mma) -> g_att (K-permuted)
    {
        dim3 grid(T_ / 64, B_ * H_);          // (8, 512)
        attn_mma_kernel<<<grid, 128, ATTN_SMEM>>>();
    }
    // 3) Output projection + bias -> d_out
    {
        float* woutt; cudaGetSymbolAddress((void**)&woutt, g_woutt);
        dim3 grid(C_ / 128, M_TOT / 128);     // (8, 128)
        tgemm_kernel<0, C_, C_><<<grid, 256, GEMM_SMEM>>>(woutt, b_out, out);
    }
}

// round 10
// speedup vs baseline: 5.8908x; 1.5620x over previous
#include <cuda_runtime.h>
#include <cuda_fp16.h>
#include <stdint.h>
#include <math.h>

// Problem constants
#define B_    32
#define T_    512
#define C_    1024
#define H_    16
#define D_    64
#define M_TOT (B_ * T_)          // 16384
#define N_QKV (3 * C_)           // 3072
#define NEG_BIG (-1.0e30f)

// Scratch (device globals: no allocations allowed)
__device__ float  g_q[B_ * H_ * T_ * D_];    // [B,H,T,D] fp32
__device__ float  g_k[B_ * H_ * T_ * D_];
__device__ float  g_v[B_ * H_ * T_ * D_];
__device__ __half g_atth[M_TOT * C_];        // attention out, fp16, kperm32 cols
__device__ __half g_xh[M_TOT * C_];          // fp16 x, kperm32 cols
__device__ __half g_wqkvth[N_QKV * C_];      // fp16 w_qkv^T [N][K], kperm32
__device__ __half g_woutth[C_ * C_];         // fp16 w_out^T [N][K], kperm32

// fp16 k-permutation within 32-element blocks: position 8t + {0..7} holds
// cols {2t,2t+1, 2t+8,2t+9, 16+2t,16+2t+1, 16+2t+8,16+2t+9} so one LDS.128
// (8 fp16) = per-row A/B fragment halves for BOTH k16 steps of a k32 block.
__device__ __host__ __forceinline__ int kperm32(int c) {   // c in [0,32)
    return 8 * ((c >> 1) & 3) + 4 * ((c >> 4) & 1) + 2 * ((c >> 3) & 1) + (c & 1);
}
__device__ __host__ __forceinline__ int kpermg(int c) {    // global col
    return (c & ~31) | kperm32(c & 31);
}

// ---------------------------------------------------------------------------
// Helpers
// ---------------------------------------------------------------------------
__device__ __forceinline__ uint32_t to_tf32_bits(float x) {
    uint32_t y;
    asm("cvt.rna.tf32.f32 %0, %1;" : "=r"(y) : "f"(x));
    return y;
}
__device__ __forceinline__ float to_tf32(float x) {
    return __uint_as_float(to_tf32_bits(x));
}

__device__ __forceinline__ uint32_t smem_u32(const void* p) {
    return (uint32_t)__cvta_generic_to_shared(p);
}
__device__ __forceinline__ void cp_async16(uint32_t dst, const void* src) {
    asm volatile("cp.async.cg.shared.global [%0], [%1], 16;\n" :: "r"(dst), "l"(src));
}
__device__ __forceinline__ void cp_commit() {
    asm volatile("cp.async.commit_group;\n" ::);
}
__device__ __forceinline__ void cp_wait0() {
    asm volatile("cp.async.wait_group 0;\n" ::);
}

__device__ __forceinline__ void mma_tf32(float* c, const uint32_t* a, const uint32_t* b) {
    asm volatile(
        "mma.sync.aligned.m16n8k8.row.col.f32.tf32.tf32.f32 "
        "{%0,%1,%2,%3}, {%4,%5,%6,%7}, {%8,%9}, {%0,%1,%2,%3};\n"
        : "+f"(c[0]), "+f"(c[1]), "+f"(c[2]), "+f"(c[3])
        : "r"(a[0]), "r"(a[1]), "r"(a[2]), "r"(a[3]),
          "r"(b[0]), "r"(b[1]));
}

__device__ __forceinline__ void mma_f16(float* c,
                                        uint32_t a0, uint32_t a1, uint32_t a2, uint32_t a3,
                                        uint32_t b0, uint32_t b1) {
    asm volatile(
        "mma.sync.aligned.m16n8k16.row.col.f32.f16.f16.f32 "
        "{%0,%1,%2,%3}, {%4,%5,%6,%7}, {%8,%9}, {%0,%1,%2,%3};\n"
        : "+f"(c[0]), "+f"(c[1]), "+f"(c[2]), "+f"(c[3])
        : "r"(a0), "r"(a1), "r"(a2), "r"(a3), "r"(b0), "r"(b1));
}

// ---------------------------------------------------------------------------
// cvt x -> fp16, kperm32 columns
// ---------------------------------------------------------------------------
__global__ __launch_bounds__(256) void cvt_x_kernel(const float* __restrict__ in)
{
    int i = blockIdx.x * blockDim.x + threadIdx.x;   // float4 id
    float4 v = ((const float4*)in)[i];
    int row = i >> 8;                 // 256 float4 per row of C_=1024
    int c   = (i & 255) * 4;
    __half* orow = g_xh + (size_t)row * C_;
    __half2 h01 = __floats2half2_rn(v.x, v.y);
    __half2 h23 = __floats2half2_rn(v.z, v.w);
    *(__half2*)(orow + kpermg(c))     = h01;   // positions even -> 4B aligned
    *(__half2*)(orow + kpermg(c + 2)) = h23;
}

// ---------------------------------------------------------------------------
// cvt + transpose: W[K][N] -> Wt[N][K] fp16 kperm32
// ---------------------------------------------------------------------------
__global__ __launch_bounds__(256) void cvt_wt_kernel(
    const float* __restrict__ in, __half* __restrict__ outp, int K, int N)
{
    __shared__ float sm[32][33];
    const int tx = threadIdx.x & 31;
    const int ty = threadIdx.x >> 5;
    const int k0 = blockIdx.x * 32;
    const int n0 = blockIdx.y * 32;
#pragma unroll
    for (int i = 0; i < 4; i++) {
        int k = ty + i * 8;
        sm[k][tx] = in[(size_t)(k0 + k) * N + n0 + tx];
    }
    __syncthreads();
#pragma unroll
    for (int i = 0; i < 4; i++) {
        int n = ty + i * 8;
        outp[(size_t)(n0 + n) * K + k0 + kperm32(tx)] = __float2half_rn(sm[tx][n]);
    }
}

// ---------------------------------------------------------------------------
// FP16 tensor-core GEMM (compile-time N,K): out = A[M,K] @ Wt[N,K]^T + bias
// CTA 128x128, kTile 64, 2-stage cp.async, fp16 smem rows stride 96
// (48 words = 16 mod 32 -> all LDS.128 phases conflict-free).
// Per k32: A 8x LDS.128, B 4x LDS.128, 32x mma.m16n8k16.
// ---------------------------------------------------------------------------
#define SROWH 96
#define STGH  (128 * SROWH)                  // halfs per stage per array
#define GEMM_SMEM (4 * STGH * 2)             // bytes

template <int EPI, int N, int K>
__global__ __launch_bounds__(256, 2) void tgemm_kernel(
    const __half* __restrict__ Wt,
    const float* __restrict__ bias,
    float* __restrict__ out)
{
    extern __shared__ __half hsm[];
    __half* As = hsm;             // [2][STGH]
    __half* Bs = hsm + 2 * STGH;  // [2][STGH]

    const __half* A = (EPI == 1) ? g_xh : g_atth;

    const int tid  = threadIdx.x;
    const int bx   = blockIdx.x;
    const int by   = blockIdx.y;
    const int warp = tid >> 5;
    const int lane = tid & 31;
    const int g    = lane >> 2;
    const int tig  = lane & 3;
    const int wm   = warp >> 2;
    const int wn   = warp & 3;

    // producer: f = tid + 256*i (i<4): row = f>>3 (0..127), chunk = f&7 (8 halfs)
    const int prow = tid >> 3;
    const int pch  = (tid & 7) * 8;
    const __half* ag = A  + ((size_t)(by * 128 + prow)) * K + pch;
    const __half* bg = Wt + ((size_t)(bx * 128 + prow)) * K + pch;
    const uint32_t a_dst = smem_u32(&As[prow * SROWH + pch]);
    const uint32_t b_dst = smem_u32(&Bs[prow * SROWH + pch]);

    float acc[4][4][4];
#pragma unroll
    for (int mt = 0; mt < 4; mt++)
#pragma unroll
        for (int nt = 0; nt < 4; nt++)
#pragma unroll
            for (int e = 0; e < 4; e++) acc[mt][nt][e] = 0.0f;

    auto load_stage = [&](int s, int k0) {
        const uint32_t sb = (uint32_t)(s * STGH * 2);
#pragma unroll
        for (int i = 0; i < 4; i++) {
            cp_async16(a_dst + sb + i * (32 * SROWH * 2), ag + k0 + (size_t)i * (32 * K));
            cp_async16(b_dst + sb + i * (32 * SROWH * 2), bg + k0 + (size_t)i * (32 * K));
        }
        cp_commit();
    };

    load_stage(0, 0);
    int stage = 0;

#pragma unroll 1
    for (int k0 = 0; k0 < K; k0 += 64) {
        cp_wait0();
        __syncthreads();
        if (k0 + 64 < K) load_stage(stage ^ 1, k0 + 64);

        const __half* as = As + stage * STGH;
        const __half* bs = Bs + stage * STGH;

#pragma unroll
        for (int blk = 0; blk < 2; blk++) {          // k32 blocks
            const int kb = blk * 32 + tig * 8;
            uint4 aLo[4], aHi[4];
#pragma unroll
            for (int mt = 0; mt < 4; mt++) {
                int r0 = wm * 64 + mt * 16 + g;
                aLo[mt] = *(const uint4*)&as[r0 * SROWH + kb];
                aHi[mt] = *(const uint4*)&as[(r0 + 8) * SROWH + kb];
            }
            uint4 bW[4];
#pragma unroll
            for (int nt = 0; nt < 4; nt++) {
                int col = wn * 32 + nt * 8 + g;
                bW[nt] = *(const uint4*)&bs[col * SROWH + kb];
            }
#pragma unroll
            for (int mt = 0; mt < 4; mt++) {
#pragma unroll
                for (int nt = 0; nt < 4; nt++) {
                    mma_f16(acc[mt][nt], aLo[mt].x, aHi[mt].x, aLo[mt].y, aHi[mt].y,
                            bW[nt].x, bW[nt].y);
                    mma_f16(acc[mt][nt], aLo[mt].z, aHi[mt].z, aLo[mt].w, aHi[mt].w,
                            bW[nt].z, bW[nt].w);
                }
            }
        }
        stage ^= 1;
    }

    // Epilogue: c0:(g,2t) c1:(g,2t+1) c2:(g+8,2t) c3:(g+8,2t+1)
#pragma unroll
    for (int mt = 0; mt < 4; mt++) {
#pragma unroll
        for (int nt = 0; nt < 4; nt++) {
#pragma unroll
            for (int e = 0; e < 4; e++) {
                int mrow = by * 128 + wm * 64 + mt * 16 + g + (e >= 2 ? 8 : 0);
                int n    = bx * 128 + wn * 32 + nt * 8 + 2 * tig + (e & 1);
                float val = acc[mt][nt][e] + bias[n];
                if (EPI == 1) {
                    int b   = mrow >> 9;
                    int t   = mrow & 511;
                    int sec = n >> 10;
                    int c   = n & 1023;
                    int h   = c >> 6;
                    int d   = c & 63;
                    float* dst = (sec == 0) ? g_q : ((sec == 1) ? g_k : g_v);
                    dst[((b * H_ + h) * T_ + t) * D_ + d] = val;
                } else {
                    out[(size_t)mrow * N + n] = val;
                }
            }
        }
    }
}

// ---------------------------------------------------------------------------
// TF32 mma causal flash attention; epilogue writes fp16 kperm32 g_atth.
// ---------------------------------------------------------------------------
#define KT_S 68
#define VT_S 72
#define PS_S 68
#define ATTN_SMEM ((64 * KT_S + 64 * VT_S + 64 * PS_S) * 4)

__global__ __launch_bounds__(128) void attn_mma_kernel()
{
    extern __shared__ float sm[];
    float* Kt = sm;
    float* Vt = sm + 64 * KT_S;
    float* Ps = Vt + 64 * VT_S;

    const int tid  = threadIdx.x;
    const int w    = tid >> 5;
    const int lane = tid & 31;
    const int g    = lane >> 2;
    const int tig  = lane & 3;
    const int qt   = blockIdx.x;
    const int bh   = blockIdx.y;
    const int b    = bh >> 4;
    const int h    = bh & 15;

    const float* Qg = g_q + (size_t)bh * T_ * D_;
    const float* Kg = g_k + (size_t)bh * T_ * D_;
    const float* Vg = g_v + (size_t)bh * T_ * D_;

    const int r0 = qt * 64 + w * 16 + g;
    const int r1 = r0 + 8;

    uint32_t qa[8][4];
#pragma unroll
    for (int ks = 0; ks < 8; ks++) {
        qa[ks][0] = to_tf32_bits(Qg[r0 * 64 + tig + 8 * ks] * 0.125f);
        qa[ks][1] = to_tf32_bits(Qg[r1 * 64 + tig + 8 * ks] * 0.125f);
        qa[ks][2] = to_tf32_bits(Qg[r0 * 64 + tig + 4 + 8 * ks] * 0.125f);
        qa[ks][3] = to_tf32_bits(Qg[r1 * 64 + tig + 4 + 8 * ks] * 0.125f);
    }

    float oacc[8][4];
#pragma unroll
    for (int nt = 0; nt < 8; nt++)
#pragma unroll
        for (int e = 0; e < 4; e++) oacc[nt][e] = 0.0f;
    float m0 = NEG_BIG, m1 = NEG_BIG, l0 = 0.0f, l1 = 0.0f;

    for (int jt = 0; jt <= qt; jt++) {
        __syncthreads();
#pragma unroll
        for (int i = 0; i < 8; i++) {
            int f4 = tid + 128 * i;
            int t  = f4 >> 4;
            int j  = f4 & 15;
            float4 kv = *(const float4*)(Kg + (size_t)(jt * 64 + t) * 64 + 4 * j);
            kv.x = to_tf32(kv.x); kv.y = to_tf32(kv.y);
            kv.z = to_tf32(kv.z); kv.w = to_tf32(kv.w);
            *(float4*)(Kt + t * KT_S + 4 * j) = kv;
            float4 vv = *(const float4*)(Vg + (size_t)(jt * 64 + t) * 64 + 4 * j);
            vv.x = to_tf32(vv.x); vv.y = to_tf32(vv.y);
            vv.z = to_tf32(vv.z); vv.w = to_tf32(vv.w);
            *(float4*)(Vt + t * VT_S + 4 * j) = vv;
        }
        __syncthreads();

        float cfr[8][4];
#pragma unroll
        for (int nt = 0; nt < 8; nt++)
#pragma unroll
            for (int e = 0; e < 4; e++) cfr[nt][e] = 0.0f;
#pragma unroll
        for (int ks = 0; ks < 8; ks++) {
#pragma unroll
            for (int nt = 0; nt < 8; nt++) {
                uint32_t bf[2];
                bf[0] = __float_as_uint(Kt[(nt * 8 + g) * KT_S + tig + 8 * ks]);
                bf[1] = __float_as_uint(Kt[(nt * 8 + g) * KT_S + tig + 4 + 8 * ks]);
                mma_tf32(cfr[nt], qa[ks], bf);
            }
        }

        if (jt == qt) {
#pragma unroll
            for (int nt = 0; nt < 8; nt++) {
                int jc = jt * 64 + nt * 8 + 2 * tig;
                if (jc     > r0) cfr[nt][0] = NEG_BIG;
                if (jc + 1 > r0) cfr[nt][1] = NEG_BIG;
                if (jc     > r1) cfr[nt][2] = NEG_BIG;
                if (jc + 1 > r1) cfr[nt][3] = NEG_BIG;
            }
        }

        float mx0 = NEG_BIG, mx1 = NEG_BIG;
#pragma unroll
        for (int nt = 0; nt < 8; nt++) {
            mx0 = fmaxf(mx0, fmaxf(cfr[nt][0], cfr[nt][1]));
            mx1 = fmaxf(mx1, fmaxf(cfr[nt][2], cfr[nt][3]));
        }
        mx0 = fmaxf(mx0, __shfl_xor_sync(0xffffffffu, mx0, 1));
        mx0 = fmaxf(mx0, __shfl_xor_sync(0xffffffffu, mx0, 2));
        mx1 = fmaxf(mx1, __shfl_xor_sync(0xffffffffu, mx1, 1));
        mx1 = fmaxf(mx1, __shfl_xor_sync(0xffffffffu, mx1, 2));
        float mn0 = fmaxf(m0, mx0), mn1 = fmaxf(m1, mx1);
        float cr0 = __expf(m0 - mn0), cr1 = __expf(m1 - mn1);
        l0 *= cr0; l1 *= cr1;
#pragma unroll
        for (int nt = 0; nt < 8; nt++) {
            oacc[nt][0] *= cr0; oacc[nt][1] *= cr0;
            oacc[nt][2] *= cr1; oacc[nt][3] *= cr1;
        }
        const int pr0 = (w * 16 + g) * PS_S;
        const int pr1 = (w * 16 + g + 8) * PS_S;
#pragma unroll
        for (int nt = 0; nt < 8; nt++) {
            int pc = nt * 8 + 2 * tig;
            float p0 = to_tf32(__expf(cfr[nt][0] - mn0));
            float p1 = to_tf32(__expf(cfr[nt][1] - mn0));
            float p2 = to_tf32(__expf(cfr[nt][2] - mn1));
            float p3 = to_tf32(__expf(cfr[nt][3] - mn1));
            l0 += p0 + p1;
            l1 += p2 + p3;
            Ps[pr0 + pc]     = p0;
            Ps[pr0 + pc + 1] = p1;
            Ps[pr1 + pc]     = p2;
            Ps[pr1 + pc + 1] = p3;
        }
        m0 = mn0; m1 = mn1;
        __syncwarp();

#pragma unroll
        for (int ks = 0; ks < 8; ks++) {
            uint32_t pa[4];
            pa[0] = __float_as_uint(Ps[pr0 + tig + 8 * ks]);
            pa[1] = __float_as_uint(Ps[pr1 + tig + 8 * ks]);
            pa[2] = __float_as_uint(Ps[pr0 + tig + 4 + 8 * ks]);
            pa[3] = __float_as_uint(Ps[pr1 + tig + 4 + 8 * ks]);
#pragma unroll
            for (int nt = 0; nt < 8; nt++) {
                uint32_t bf[2];
                bf[0] = __float_as_uint(Vt[(tig + 8 * ks) * VT_S + nt * 8 + g]);
                bf[1] = __float_as_uint(Vt[(tig + 4 + 8 * ks) * VT_S + nt * 8 + g]);
                mma_tf32(oacc[nt], pa, bf);
            }
        }
        __syncwarp();
    }

    l0 += __shfl_xor_sync(0xffffffffu, l0, 1);
    l0 += __shfl_xor_sync(0xffffffffu, l0, 2);
    l1 += __shfl_xor_sync(0xffffffffu, l1, 1);
    l1 += __shfl_xor_sync(0xffffffffu, l1, 2);
    float i0 = 1.0f / l0, i1 = 1.0f / l1;

    // write fp16, kperm32-permuted (pairs stay adjacent; positions even)
    __half* out0 = g_atth + (size_t)(b * T_ + r0) * C_ + h * 64;
    __half* out1 = g_atth + (size_t)(b * T_ + r1) * C_ + h * 64;
#pragma unroll
    for (int nt = 0; nt < 8; nt++) {
        int pc = nt * 8 + 2 * tig;
        int pp = kpermg(pc);
        *(__half2*)(out0 + pp) = __floats2half2_rn(oacc[nt][0] * i0, oacc[nt][1] * i0);
        *(__half2*)(out1 + pp) = __floats2half2_rn(oacc[nt][2] * i1, oacc[nt][3] * i1);
    }
}

// ---------------------------------------------------------------------------
// Launch
// ---------------------------------------------------------------------------
extern "C" void kernel_launch(void* const* d_in, const int* in_sizes, int n_in,
                              void* d_out, int out_size)
{
    const float* x     = (const float*)d_in[0];
    const float* w_qkv = (const float*)d_in[1];
    const float* b_qkv = (const float*)d_in[2];
    const float* w_out = (const float*)d_in[3];
    const float* b_out = (const float*)d_in[4];
    float* out = (float*)d_out;

    cudaFuncSetAttribute(attn_mma_kernel,
                         cudaFuncAttributeMaxDynamicSharedMemorySize, ATTN_SMEM);
    cudaFuncSetAttribute(tgemm_kernel<1, N_QKV, C_>,
                         cudaFuncAttributeMaxDynamicSharedMemorySize, GEMM_SMEM);
    cudaFuncSetAttribute(tgemm_kernel<0, C_, C_>,
                         cudaFuncAttributeMaxDynamicSharedMemorySize, GEMM_SMEM);

    __half* wqkvt; cudaGetSymbolAddress((void**)&wqkvt, g_wqkvth);
    __half* woutt; cudaGetSymbolAddress((void**)&woutt, g_woutth);

    // 0) fp16 + permute/transpose prep
    {
        int n4x = (M_TOT * C_) / 4;
        cvt_x_kernel<<<n4x / 256, 256>>>(x);
        dim3 g1(C_ / 32, N_QKV / 32);
        cvt_wt_kernel<<<g1, 256>>>(w_qkv, wqkvt, C_, N_QKV);
        dim3 g2(C_ / 32, C_ / 32);
        cvt_wt_kernel<<<g2, 256>>>(w_out, woutt, C_, C_);
    }
    // 1) QKV projection + bias -> g_q/g_k/g_v [B,H,T,D]
    {
        dim3 grid(N_QKV / 128, M_TOT / 128);  // (24, 128)
        tgemm_kernel<1, N_QKV, C_><<<grid, 256, GEMM_SMEM>>>(wqkvt, b_qkv, nullptr);
    }
    // 2) Causal flash attention (tf32 mma) -> g_atth (fp16, kperm32)
    {
        dim3 grid(T_ / 64, B_ * H_);          // (8, 512)
        attn_mma_kernel<<<grid, 128, ATTN_SMEM>>>();
    }
    // 3) Output projection + bias -> d_out
    {
        dim3 grid(C_ / 128, M_TOT / 128);     // (8, 128)
        tgemm_kernel<0, C_, C_><<<grid, 256, GEMM_SMEM>>>(woutt, b_out, out);
    }
}

// round 14
// speedup vs baseline: 6.8524x; 1.1632x over previous
#include <cuda_runtime.h>
#include <cuda_fp16.h>
#include <stdint.h>
#include <math.h>

// Problem constants
#define B_    32
#define T_    512
#define C_    1024
#define H_    16
#define D_    64
#define M_TOT (B_ * T_)          // 16384
#define N_QKV (3 * C_)           // 3072
#define NEG_BIG (-1.0e30f)

// Scratch (device globals: no allocations allowed)
__device__ __half g_qh[B_ * H_ * T_ * D_];   // [B,H,T,D], D kperm32
__device__ __half g_kh[B_ * H_ * T_ * D_];   // [B,H,T,D], D kperm32
__device__ __half g_vth[B_ * H_ * D_ * T_];  // [B,H,D,T], T kperm32 (V^T)
__device__ __half g_atth[M_TOT * C_];        // attention out, fp16, kperm32 cols
__device__ __half g_xh[M_TOT * C_];          // fp16 x, kperm32 cols
__device__ __half g_wqkvth[N_QKV * C_];      // fp16 w_qkv^T [N][K], kperm32
__device__ __half g_woutth[C_ * C_];         // fp16 w_out^T [N][K], kperm32

// fp16 k-permutation within 32-element blocks: position 8t + {0..7} holds
// cols {2t,2t+1, 2t+8,2t+9, 16+2t,16+2t+1, 16+2t+8,16+2t+9} so one LDS.128
// (8 fp16) = per-row mma fragment halves for BOTH k16 steps of a k32 block.
__device__ __host__ __forceinline__ int kperm32(int c) {   // c in [0,32)
    return 8 * ((c >> 1) & 3) + 4 * ((c >> 4) & 1) + 2 * ((c >> 3) & 1) + (c & 1);
}
__device__ __host__ __forceinline__ int kpermg(int c) {    // global col
    return (c & ~31) | kperm32(c & 31);
}

// ---------------------------------------------------------------------------
// Helpers
// ---------------------------------------------------------------------------
__device__ __forceinline__ uint32_t smem_u32(const void* p) {
    return (uint32_t)__cvta_generic_to_shared(p);
}
__device__ __forceinline__ void cp_async16(uint32_t dst, const void* src) {
    asm volatile("cp.async.cg.shared.global [%0], [%1], 16;\n" :: "r"(dst), "l"(src));
}
__device__ __forceinline__ void cp_commit() {
    asm volatile("cp.async.commit_group;\n" ::);
}
__device__ __forceinline__ void cp_wait0() {
    asm volatile("cp.async.wait_group 0;\n" ::);
}

__device__ __forceinline__ void mma_f16(float* c,
                                        uint32_t a0, uint32_t a1, uint32_t a2, uint32_t a3,
                                        uint32_t b0, uint32_t b1) {
    asm volatile(
        "mma.sync.aligned.m16n8k16.row.col.f32.f16.f16.f32 "
        "{%0,%1,%2,%3}, {%4,%5,%6,%7}, {%8,%9}, {%0,%1,%2,%3};\n"
        : "+f"(c[0]), "+f"(c[1]), "+f"(c[2]), "+f"(c[3])
        : "r"(a0), "r"(a1), "r"(a2), "r"(a3), "r"(b0), "r"(b1));
}

__device__ __forceinline__ uint32_t pack_h2(float lo, float hi) {
    __half2 h = __floats2half2_rn(lo, hi);
    return *(uint32_t*)&h;
}

// ---------------------------------------------------------------------------
// cvt x -> fp16, kperm32 columns
// ---------------------------------------------------------------------------
__global__ __launch_bounds__(256) void cvt_x_kernel(const float* __restrict__ in)
{
    int i = blockIdx.x * blockDim.x + threadIdx.x;   // float4 id
    float4 v = ((const float4*)in)[i];
    int row = i >> 8;                 // 256 float4 per row of C_=1024
    int c   = (i & 255) * 4;
    __half* orow = g_xh + (size_t)row * C_;
    *(__half2*)(orow + kpermg(c))     = __floats2half2_rn(v.x, v.y);
    *(__half2*)(orow + kpermg(c + 2)) = __floats2half2_rn(v.z, v.w);
}

// ---------------------------------------------------------------------------
// cvt + transpose: W[K][N] -> Wt[N][K] fp16 kperm32
// ---------------------------------------------------------------------------
__global__ __launch_bounds__(256) void cvt_wt_kernel(
    const float* __restrict__ in, __half* __restrict__ outp, int K, int N)
{
    __shared__ float sm[32][33];
    const int tx = threadIdx.x & 31;
    const int ty = threadIdx.x >> 5;
    const int k0 = blockIdx.x * 32;
    const int n0 = blockIdx.y * 32;
#pragma unroll
    for (int i = 0; i < 4; i++) {
        int k = ty + i * 8;
        sm[k][tx] = in[(size_t)(k0 + k) * N + n0 + tx];
    }
    __syncthreads();
#pragma unroll
    for (int i = 0; i < 4; i++) {
        int n = ty + i * 8;
        outp[(size_t)(n0 + n) * K + k0 + kperm32(tx)] = __float2half_rn(sm[tx][n]);
    }
}

// ---------------------------------------------------------------------------
// FP16 tensor-core GEMM (R10 proven): out = A[M,K] @ Wt[N,K]^T + bias
// CTA 128x128, kTile 64, 2-stage cp.async, fp16 smem rows stride 96.
// EPI==1: epilogue writes fp16 g_qh/g_kh (D kperm32) and g_vth (V^T, T kperm32)
// EPI==0: writes fp32 out[M][N]
// ---------------------------------------------------------------------------
#define SROWH 96
#define STGH  (128 * SROWH)                  // halfs per stage per array
#define GEMM_SMEM (4 * STGH * 2)             // bytes

template <int EPI, int N, int K>
__global__ __launch_bounds__(256, 2) void tgemm_kernel(
    const __half* __restrict__ Wt,
    const float* __restrict__ bias,
    float* __restrict__ out)
{
    extern __shared__ __half hsm[];
    __half* As = hsm;             // [2][STGH]
    __half* Bs = hsm + 2 * STGH;  // [2][STGH]

    const __half* A = (EPI == 1) ? g_xh : g_atth;

    const int tid  = threadIdx.x;
    const int bx   = blockIdx.x;
    const int by   = blockIdx.y;
    const int warp = tid >> 5;
    const int lane = tid & 31;
    const int g    = lane >> 2;
    const int tig  = lane & 3;
    const int wm   = warp >> 2;
    const int wn   = warp & 3;

    const int prow = tid >> 3;                // 0..31
    const int pch  = (tid & 7) * 8;
    const __half* ag = A  + ((size_t)(by * 128 + prow)) * K + pch;
    const __half* bg = Wt + ((size_t)(bx * 128 + prow)) * K + pch;
    const uint32_t a_dst = smem_u32(&As[prow * SROWH + pch]);
    const uint32_t b_dst = smem_u32(&Bs[prow * SROWH + pch]);

    float acc[4][4][4];
#pragma unroll
    for (int mt = 0; mt < 4; mt++)
#pragma unroll
        for (int nt = 0; nt < 4; nt++)
#pragma unroll
            for (int e = 0; e < 4; e++) acc[mt][nt][e] = 0.0f;

    auto load_stage = [&](int s, int k0) {
        const uint32_t sb = (uint32_t)(s * STGH * 2);
#pragma unroll
        for (int i = 0; i < 4; i++) {        // rows prow + 32*i -> 0..127
            cp_async16(a_dst + sb + i * (32 * SROWH * 2), ag + k0 + (size_t)i * (32 * K));
            cp_async16(b_dst + sb + i * (32 * SROWH * 2), bg + k0 + (size_t)i * (32 * K));
        }
        cp_commit();
    };

    load_stage(0, 0);
    int stage = 0;

#pragma unroll 1
    for (int k0 = 0; k0 < K; k0 += 64) {
        cp_wait0();
        __syncthreads();
        if (k0 + 64 < K) load_stage(stage ^ 1, k0 + 64);

        const __half* as = As + stage * STGH;
        const __half* bs = Bs + stage * STGH;

#pragma unroll
        for (int blk = 0; blk < 2; blk++) {
            const int kb = blk * 32 + tig * 8;
            uint4 aLo[4], aHi[4];
#pragma unroll
            for (int mt = 0; mt < 4; mt++) {
                int r0 = wm * 64 + mt * 16 + g;
                aLo[mt] = *(const uint4*)&as[r0 * SROWH + kb];
                aHi[mt] = *(const uint4*)&as[(r0 + 8) * SROWH + kb];
            }
            uint4 bW[4];
#pragma unroll
            for (int nt = 0; nt < 4; nt++) {
                int col = wn * 32 + nt * 8 + g;
                bW[nt] = *(const uint4*)&bs[col * SROWH + kb];
            }
#pragma unroll
            for (int mt = 0; mt < 4; mt++) {
#pragma unroll
                for (int nt = 0; nt < 4; nt++) {
                    mma_f16(acc[mt][nt], aLo[mt].x, aHi[mt].x, aLo[mt].y, aHi[mt].y,
                            bW[nt].x, bW[nt].y);
                    mma_f16(acc[mt][nt], aLo[mt].z, aHi[mt].z, aLo[mt].w, aHi[mt].w,
                            bW[nt].z, bW[nt].w);
                }
            }
        }
        stage ^= 1;
    }

    // Epilogue: pairs (e0,e1) = (row r, n..n+1), (e2,e3) = (row r+8, n..n+1)
#pragma unroll
    for (int mt = 0; mt < 4; mt++) {
#pragma unroll
        for (int nt = 0; nt < 4; nt++) {
            int r0   = by * 128 + wm * 64 + mt * 16 + g;
            int n    = bx * 128 + wn * 32 + nt * 8 + 2 * tig;
            float v0 = acc[mt][nt][0] + bias[n];
            float v1 = acc[mt][nt][1] + bias[n + 1];
            float v2 = acc[mt][nt][2] + bias[n];
            float v3 = acc[mt][nt][3] + bias[n + 1];
            if (EPI == 1) {
                int sec = n >> 10;
                int c   = n & 1023;
                int h   = c >> 6;
                int d   = c & 63;
                int b0  = r0 >> 9, t0 = r0 & 511;
                int b1  = (r0 + 8) >> 9, t1 = (r0 + 8) & 511;
                if (sec < 2) {
                    __half* dst = (sec == 0) ? g_qh : g_kh;
                    int dp = kpermg(d);
                    *(__half2*)&dst[((size_t)(b0 * H_ + h) * T_ + t0) * D_ + dp] =
                        __floats2half2_rn(v0, v1);
                    *(__half2*)&dst[((size_t)(b1 * H_ + h) * T_ + t1) * D_ + dp] =
                        __floats2half2_rn(v2, v3);
                } else {
                    // V^T: [B,H,D,T], T kperm32
                    int tp0 = kpermg(t0), tp1 = kpermg(t1);
                    size_t base = (size_t)(b0 * H_ + h) * D_;
                    g_vth[(base + d)     * T_ + tp0] = __float2half_rn(v0);
                    g_vth[(base + d + 1) * T_ + tp0] = __float2half_rn(v1);
                    size_t base1 = (size_t)(b1 * H_ + h) * D_;
                    g_vth[(base1 + d)     * T_ + tp1] = __float2half_rn(v2);
                    g_vth[(base1 + d + 1) * T_ + tp1] = __float2half_rn(v3);
                }
            } else {
                out[(size_t)r0 * N + n]           = v0;
                out[(size_t)r0 * N + n + 1]       = v1;
                out[(size_t)(r0 + 8) * N + n]     = v2;
                out[(size_t)(r0 + 8) * N + n + 1] = v3;
            }
        }
    }
}

// ---------------------------------------------------------------------------
// FP16 mma causal flash attention.
// CTA: 128 threads (4 warps), 64 query rows; warp owns 16 rows.
// Staging (128 threads): 64 rows x 8 chunks = 512 chunks, 16 rows per iter.
// ---------------------------------------------------------------------------
#define AS_S 96   // smem stride in halfs (192B rows; conflict-free for uint4)
#define ATTN_SMEM (3 * 64 * AS_S * 2)

__global__ __launch_bounds__(128) void attn_f16_kernel()
{
    extern __shared__ __half ash[];
    __half* Qs = ash;
    __half* Kt = ash + 64 * AS_S;
    __half* Vt = ash + 2 * 64 * AS_S;

    const int tid  = threadIdx.x;
    const int w    = tid >> 5;
    const int lane = tid & 31;
    const int g    = lane >> 2;
    const int tig  = lane & 3;
    const int qt   = blockIdx.x;
    const int bh   = blockIdx.y;
    const int b    = bh >> 4;
    const int h    = bh & 15;

    const __half* Qg = g_qh  + (size_t)bh * T_ * D_;
    const __half* Kg = g_kh  + (size_t)bh * T_ * D_;
    const __half* Vg = g_vth + (size_t)bh * D_ * T_;

    const int r0 = qt * 64 + w * 16 + g;   // global q row (lower 8-group)
    const int r1 = r0 + 8;

    const int rch = tid >> 3;              // 0..15
    const int cc  = (tid & 7) * 8;         // 0..56

    // Stage Q tile: rows rch + 16*i (i<4) -> 0..63
    {
        uint32_t qdst = smem_u32(&Qs[rch * AS_S + cc]);
#pragma unroll
        for (int i = 0; i < 4; i++) {
            int r = rch + 16 * i;
            cp_async16(qdst + i * (16 * AS_S * 2),
                       Qg + (size_t)(qt * 64 + r) * D_ + cc);
        }
        cp_commit();
    }
    cp_wait0();
    __syncthreads();

    // Q fragments (held in registers for the whole loop)
    uint4 qlo[2], qhi[2];
#pragma unroll
    for (int blk = 0; blk < 2; blk++) {
        qlo[blk] = *(const uint4*)&Qs[(w * 16 + g) * AS_S + blk * 32 + tig * 8];
        qhi[blk] = *(const uint4*)&Qs[(w * 16 + g + 8) * AS_S + blk * 32 + tig * 8];
    }

    float oacc[8][4];
#pragma unroll
    for (int nt = 0; nt < 8; nt++)
#pragma unroll
        for (int e = 0; e < 4; e++) oacc[nt][e] = 0.0f;
    float m0 = NEG_BIG, m1 = NEG_BIG, l0 = 0.0f, l1 = 0.0f;

    const uint32_t kdst = smem_u32(&Kt[rch * AS_S + cc]);
    const uint32_t vdst = smem_u32(&Vt[rch * AS_S + cc]);

    for (int jt = 0; jt <= qt; jt++) {
        __syncthreads();    // previous-iteration consumers done with Kt/Vt
        // Stage K tile (rows=keys 0..63) and V^T tile (rows=d 0..63)
#pragma unroll
        for (int i = 0; i < 4; i++) {
            int r = rch + 16 * i;
            cp_async16(kdst + i * (16 * AS_S * 2),
                       Kg + (size_t)(jt * 64 + r) * D_ + cc);
            cp_async16(vdst + i * (16 * AS_S * 2),
                       Vg + (size_t)r * T_ + jt * 64 + cc);
        }
        cp_commit();
        cp_wait0();
        __syncthreads();

        // S = Q K^T  (16 x 64 per warp)
        float cfr[8][4];
#pragma unroll
        for (int nt = 0; nt < 8; nt++)
#pragma unroll
            for (int e = 0; e < 4; e++) cfr[nt][e] = 0.0f;
#pragma unroll
        for (int blk = 0; blk < 2; blk++) {
#pragma unroll
            for (int nt = 0; nt < 8; nt++) {
                uint4 kb = *(const uint4*)&Kt[(nt * 8 + g) * AS_S + blk * 32 + tig * 8];
                mma_f16(cfr[nt], qlo[blk].x, qhi[blk].x, qlo[blk].y, qhi[blk].y,
                        kb.x, kb.y);
                mma_f16(cfr[nt], qlo[blk].z, qhi[blk].z, qlo[blk].w, qhi[blk].w,
                        kb.z, kb.w);
            }
        }
        // scale 1/sqrt(D)
#pragma unroll
        for (int nt = 0; nt < 8; nt++)
#pragma unroll
            for (int e = 0; e < 4; e++) cfr[nt][e] *= 0.125f;

        // causal mask on diagonal tile
        if (jt == qt) {
#pragma unroll
            for (int nt = 0; nt < 8; nt++) {
                int jc = jt * 64 + nt * 8 + 2 * tig;
                if (jc     > r0) cfr[nt][0] = NEG_BIG;
                if (jc + 1 > r0) cfr[nt][1] = NEG_BIG;
                if (jc     > r1) cfr[nt][2] = NEG_BIG;
                if (jc + 1 > r1) cfr[nt][3] = NEG_BIG;
            }
        }

        // online softmax
        float mx0 = NEG_BIG, mx1 = NEG_BIG;
#pragma unroll
        for (int nt = 0; nt < 8; nt++) {
            mx0 = fmaxf(mx0, fmaxf(cfr[nt][0], cfr[nt][1]));
            mx1 = fmaxf(mx1, fmaxf(cfr[nt][2], cfr[nt][3]));
        }
        mx0 = fmaxf(mx0, __shfl_xor_sync(0xffffffffu, mx0, 1));
        mx0 = fmaxf(mx0, __shfl_xor_sync(0xffffffffu, mx0, 2));
        mx1 = fmaxf(mx1, __shfl_xor_sync(0xffffffffu, mx1, 1));
        mx1 = fmaxf(mx1, __shfl_xor_sync(0xffffffffu, mx1, 2));
        float mn0 = fmaxf(m0, mx0), mn1 = fmaxf(m1, mx1);
        float cr0 = __expf(m0 - mn0), cr1 = __expf(m1 - mn1);
        l0 *= cr0; l1 *= cr1;
#pragma unroll
        for (int nt = 0; nt < 8; nt++) {
            oacc[nt][0] *= cr0; oacc[nt][1] *= cr0;
            oacc[nt][2] *= cr1; oacc[nt][3] *= cr1;
        }

        // exp -> P fragments (c-layout == a-layout; no smem round trip)
        uint32_t pa0[4], pa1[4], pa2[4], pa3[4];   // per k16 step ks
#pragma unroll
        for (int ks = 0; ks < 4; ks++) {
            float p00 = __expf(cfr[2 * ks][0] - mn0);
            float p01 = __expf(cfr[2 * ks][1] - mn0);
            float p02 = __expf(cfr[2 * ks][2] - mn1);
            float p03 = __expf(cfr[2 * ks][3] - mn1);
            float p10 = __expf(cfr[2 * ks + 1][0] - mn0);
            float p11 = __expf(cfr[2 * ks + 1][1] - mn0);
            float p12 = __expf(cfr[2 * ks + 1][2] - mn1);
            float p13 = __expf(cfr[2 * ks + 1][3] - mn1);
            l0 += p00 + p01 + p10 + p11;
            l1 += p02 + p03 + p12 + p13;
            pa0[ks] = pack_h2(p00, p01);
            pa1[ks] = pack_h2(p02, p03);
            pa2[ks] = pack_h2(p10, p11);
            pa3[ks] = pack_h2(p12, p13);
        }
        m0 = mn0; m1 = mn1;

        // O += P V   (B from V^T tile)
#pragma unroll
        for (int blk = 0; blk < 2; blk++) {
#pragma unroll
            for (int nt = 0; nt < 8; nt++) {
                uint4 vb = *(const uint4*)&Vt[(nt * 8 + g) * AS_S + blk * 32 + tig * 8];
                mma_f16(oacc[nt], pa0[2 * blk], pa1[2 * blk], pa2[2 * blk], pa3[2 * blk],
                        vb.x, vb.y);
                mma_f16(oacc[nt], pa0[2 * blk + 1], pa1[2 * blk + 1],
                        pa2[2 * blk + 1], pa3[2 * blk + 1], vb.z, vb.w);
            }
        }
    }

    // finalize: reduce l over tig quad, normalize, write fp16 kperm32 g_atth
    l0 += __shfl_xor_sync(0xffffffffu, l0, 1);
    l0 += __shfl_xor_sync(0xffffffffu, l0, 2);
    l1 += __shfl_xor_sync(0xffffffffu, l1, 1);
    l1 += __shfl_xor_sync(0xffffffffu, l1, 2);
    float i0 = 1.0f / l0, i1 = 1.0f / l1;

    __half* out0 = g_atth + (size_t)(b * T_ + r0) * C_ + h * 64;
    __half* out1 = g_atth + (size_t)(b * T_ + r1) * C_ + h * 64;
#pragma unroll
    for (int nt = 0; nt < 8; nt++) {
        int pc = nt * 8 + 2 * tig;
        int pp = kpermg(pc);
        *(__half2*)(out0 + pp) = __floats2half2_rn(oacc[nt][0] * i0, oacc[nt][1] * i0);
        *(__half2*)(out1 + pp) = __floats2half2_rn(oacc[nt][2] * i1, oacc[nt][3] * i1);
    }
}

// ---------------------------------------------------------------------------
// Launch
// ---------------------------------------------------------------------------
extern "C" void kernel_launch(void* const* d_in, const int* in_sizes, int n_in,
                              void* d_out, int out_size)
{
    const float* x     = (const float*)d_in[0];
    const float* w_qkv = (const float*)d_in[1];
    const float* b_qkv = (const float*)d_in[2];
    const float* w_out = (const float*)d_in[3];
    const float* b_out = (const float*)d_in[4];
    float* out = (float*)d_out;

    cudaFuncSetAttribute(attn_f16_kernel,
                         cudaFuncAttributeMaxDynamicSharedMemorySize, ATTN_SMEM);
    cudaFuncSetAttribute(tgemm_kernel<1, N_QKV, C_>,
                         cudaFuncAttributeMaxDynamicSharedMemorySize, GEMM_SMEM);
    cudaFuncSetAttribute(tgemm_kernel<0, C_, C_>,
                         cudaFuncAttributeMaxDynamicSharedMemorySize, GEMM_SMEM);

    __half* wqkvt; cudaGetSymbolAddress((void**)&wqkvt, g_wqkvth);
    __half* woutt; cudaGetSymbolAddress((void**)&woutt, g_woutth);

    // 0) fp16 + permute/transpose prep
    {
        int n4x = (M_TOT * C_) / 4;
        cvt_x_kernel<<<n4x / 256, 256>>>(x);
        dim3 g1(C_ / 32, N_QKV / 32);
        cvt_wt_kernel<<<g1, 256>>>(w_qkv, wqkvt, C_, N_QKV);
        dim3 g2(C_ / 32, C_ / 32);
        cvt_wt_kernel<<<g2, 256>>>(w_out, woutt, C_, C_);
    }
    // 1) QKV projection + bias -> g_qh/g_kh (fp16) and g_vth (V^T fp16)
    {
        dim3 grid(N_QKV / 128, M_TOT / 128);  // (24, 128)
        tgemm_kernel<1, N_QKV, C_><<<grid, 256, GEMM_SMEM>>>(wqkvt, b_qkv, nullptr);
    }
    // 2) Causal flash attention (fp16 mma) -> g_atth (fp16, kperm32)
    {
        dim3 grid(T_ / 64, B_ * H_);          // (8, 512)
        attn_f16_kernel<<<grid, 128, ATTN_SMEM>>>();
    }
    // 3) Output projection + bias -> d_out
    {
        dim3 grid(C_ / 128, M_TOT / 128);     // (8, 128)
        tgemm_kernel<0, C_, C_><<<grid, 256, GEMM_SMEM>>>(woutt, b_out, out);
    }
}